// round 2
// baseline (speedup 1.0000x reference)
#include <cuda_runtime.h>
#include <cuda_bf16.h>
#include <cstdint>

// Problem constants
#define BATCH 2
#define SEQ_N 4096
#define SEQ_M 4096
#define DIM_C 512
#define HEADS 8
#define HDIM  64

// ---------------------------------------------------------------------------
// Scratch (no allocations allowed -> __device__ globals)
// ---------------------------------------------------------------------------
__device__ float g_Q[BATCH * SEQ_N * DIM_C];
__device__ float g_K[BATCH * SEQ_M * DIM_C];
__device__ float g_V[BATCH * SEQ_M * DIM_C];
__device__ float g_O[BATCH * SEQ_N * DIM_C];
// packed mask bits, transposed: g_Mbits[(b*128 + w)*4096 + n], bit j of word w
// = mask[b, n, w*32 + j]
__device__ uint32_t g_Mbits[BATCH * 128 * SEQ_N];
__device__ int g_maskBool;   // 1 if mask stored as 1-byte bool, 0 if int32

// ---------------------------------------------------------------------------
// Mask dtype detection: bool storage -> random 0/1 BYTES -> many aligned
// uint32 words exceed 1. int32 storage -> every word is exactly 0 or 1.
// Scan first 4096 bytes (1024 words); deterministic given the input.
// ---------------------------------------------------------------------------
__global__ void detect_mask_kernel(const uint32_t* __restrict__ m)
{
    __shared__ int found;
    if (threadIdx.x == 0) found = 0;
    __syncthreads();
    uint32_t v = m[threadIdx.x] | m[threadIdx.x + 256] |
                 m[threadIdx.x + 512] | m[threadIdx.x + 768];
    if (v > 1u) atomicOr(&found, 1);
    __syncthreads();
    if (threadIdx.x == 0) g_maskBool = found;
}

// ---------------------------------------------------------------------------
// Pack mask into transposed bitmask. One block per (b,n) row, thread w builds
// the 32-key word w. Input reads are coalesced; output scatter is tiny (4MB).
// ---------------------------------------------------------------------------
__global__ __launch_bounds__(128) void pack_mask_kernel(
    const unsigned char* __restrict__ mraw, uint32_t* __restrict__ out)
{
    const int bn = blockIdx.x;           // b*4096 + n
    const int w  = threadIdx.x;          // 0..127
    const int b  = bn >> 12;
    const int n  = bn & 4095;
    uint32_t bits = 0;
    if (g_maskBool) {
        const uint32_t* p =
            (const uint32_t*)(mraw + (size_t)bn * 4096) + w * 8;
#pragma unroll
        for (int i = 0; i < 8; ++i) {
            uint32_t v = p[i];
#pragma unroll
            for (int j = 0; j < 4; ++j)
                if ((v >> (j * 8)) & 0xFFu) bits |= 1u << (i * 4 + j);
        }
    } else {
        const int* p = (const int*)mraw + (size_t)bn * 4096 + w * 32;
#pragma unroll
        for (int i = 0; i < 32; ++i)
            if (p[i] != 0) bits |= 1u << i;
    }
    out[((size_t)(b * 128 + w)) * 4096 + n] = bits;
}

// ---------------------------------------------------------------------------
// SGEMM: Y[M,512] = A[M,512] @ W[512,512] + bias
// Block tile 128x64, BK=16, 256 threads, 8x4 microtile per thread.
// ---------------------------------------------------------------------------
__global__ __launch_bounds__(256) void gemm512_kernel(
    const float* __restrict__ A, const float* __restrict__ W,
    const float* __restrict__ bias, float* __restrict__ Y)
{
    const int BM = 128, BN = 64, BK = 16;
    __shared__ __align__(16) float As[BK][BM];   // 8 KB
    __shared__ __align__(16) float Bs[BK][BN];   // 4 KB

    const int tid = threadIdx.x;
    const int tx = tid & 15;        // 0..15 (col group)
    const int ty = tid >> 4;        // 0..15 (row group)
    const int row0 = blockIdx.y * BM;
    const int col0 = blockIdx.x * BN;

    float acc[8][4];
#pragma unroll
    for (int i = 0; i < 8; ++i)
#pragma unroll
        for (int j = 0; j < 4; ++j) acc[i][j] = 0.f;

    const int am = tid >> 2;              // 0..63
    const int ak = (tid & 3) * 4;         // 0,4,8,12
    const int br = tid >> 4;              // 0..15
    const int bc = (tid & 15) * 4;        // 0..60

    for (int k0 = 0; k0 < 512; k0 += BK) {
        float4 a0 = *(const float4*)&A[(size_t)(row0 + am) * 512 + k0 + ak];
        float4 a1 = *(const float4*)&A[(size_t)(row0 + am + 64) * 512 + k0 + ak];
        As[ak + 0][am] = a0.x; As[ak + 1][am] = a0.y;
        As[ak + 2][am] = a0.z; As[ak + 3][am] = a0.w;
        As[ak + 0][am + 64] = a1.x; As[ak + 1][am + 64] = a1.y;
        As[ak + 2][am + 64] = a1.z; As[ak + 3][am + 64] = a1.w;
        float4 w4 = *(const float4*)&W[(size_t)(k0 + br) * 512 + col0 + bc];
        *(float4*)&Bs[br][bc] = w4;
        __syncthreads();

#pragma unroll
        for (int k = 0; k < BK; ++k) {
            float af[8], bf[4];
            float4 afa = *(const float4*)&As[k][ty * 8];
            float4 afb = *(const float4*)&As[k][ty * 8 + 4];
            af[0] = afa.x; af[1] = afa.y; af[2] = afa.z; af[3] = afa.w;
            af[4] = afb.x; af[5] = afb.y; af[6] = afb.z; af[7] = afb.w;
            float4 bfv = *(const float4*)&Bs[k][tx * 4];
            bf[0] = bfv.x; bf[1] = bfv.y; bf[2] = bfv.z; bf[3] = bfv.w;
#pragma unroll
            for (int i = 0; i < 8; ++i)
#pragma unroll
                for (int j = 0; j < 4; ++j)
                    acc[i][j] = fmaf(af[i], bf[j], acc[i][j]);
        }
        __syncthreads();
    }

    float4 bia = *(const float4*)&bias[col0 + tx * 4];
#pragma unroll
    for (int i = 0; i < 8; ++i) {
        float4 r;
        r.x = acc[i][0] + bia.x;
        r.y = acc[i][1] + bia.y;
        r.z = acc[i][2] + bia.z;
        r.w = acc[i][3] + bia.w;
        *(float4*)&Y[(size_t)(row0 + ty * 8 + i) * 512 + col0 + tx * 4] = r;
    }
}

// ---------------------------------------------------------------------------
// RoPE 2D (in place on (B, Nseq, H, 64) layout), optional extra scale.
// Per head: dims [0,32) rotated with pos_y, [32,64) with pos_x.
// Pair (ii, ii+16) inside each 32-block, inv_freq = 100^{-ii/16}.
// ---------------------------------------------------------------------------
__global__ void rope2d_kernel(float* __restrict__ t, const int* __restrict__ pos,
                              float qscale, int total /* B*Nseq*H*32 */)
{
    int idx = blockIdx.x * blockDim.x + threadIdx.x;
    if (idx >= total) return;
    int pair = idx & 31;
    int h    = (idx >> 5) & 7;
    int n    = (idx >> 8) & 4095;   // SEQ = 4096
    int b    = idx >> 20;
    int blk  = pair >> 4;           // 0 = y half, 1 = x half
    int ii   = pair & 15;

    // 100^{-ii/16} = exp2(-ii * log2(100)/16)
    float invf = exp2f(-(float)ii * 0.41524101186092864f);
    int p = pos[((size_t)(b * 4096 + n)) * 2 + blk];
    float ang = (float)p * invf;
    float sn, cs;
    sincosf(ang, &sn, &cs);

    size_t base = ((size_t)(b * 4096 + n) * 8 + h) * 64 + blk * 32 + ii;
    float v1 = t[base];
    float v2 = t[base + 16];
    t[base]      = (v1 * cs - v2 * sn) * qscale;
    t[base + 16] = (v2 * cs + v1 * sn) * qscale;
}

// ---------------------------------------------------------------------------
// Flash attention (fp32). 128 queries/block, 1 query per thread.
// K/V tiles of 64 keys in smem; mask from packed transposed bitmask
// (coalesced per-thread loads, 2 words per 64-key tile).
// Online softmax in chunks of 16 keys.
// ---------------------------------------------------------------------------
__global__ __launch_bounds__(128) void attn_kernel(
    const float* __restrict__ Q, const float* __restrict__ K,
    const float* __restrict__ V, const uint32_t* __restrict__ Mbits,
    float* __restrict__ O)
{
    const int b  = blockIdx.z;
    const int h  = blockIdx.y;
    const int q0 = blockIdx.x * 128;
    const int t  = threadIdx.x;
    const int n  = q0 + t;

    __shared__ __align__(16) float Ks[64 * 64];     // 16 KB
    __shared__ __align__(16) float Vs[64 * 64];     // 16 KB

    float q[64];
    {
        const float* qp = &Q[((size_t)(b * 4096 + n)) * 512 + h * 64];
#pragma unroll
        for (int d4 = 0; d4 < 16; ++d4) {
            float4 v = *(const float4*)(qp + d4 * 4);
            q[d4 * 4 + 0] = v.x; q[d4 * 4 + 1] = v.y;
            q[d4 * 4 + 2] = v.z; q[d4 * 4 + 3] = v.w;
        }
    }

    float o[64];
#pragma unroll
    for (int d = 0; d < 64; ++d) o[d] = 0.f;
    float m = -1e30f, l = 0.f;

    const int trow = t >> 4;   // 0..7
    const int tcol = t & 15;   // 0..15

    for (int m0 = 0; m0 < SEQ_M; m0 += 64) {
        // --- cooperative K/V tile loads ---
#pragma unroll
        for (int it = 0; it < 8; ++it) {
            int j = it * 8 + trow;
            size_t gbase = ((size_t)(b * 4096 + m0 + j)) * 512 + h * 64 + tcol * 4;
            *(float4*)&Ks[j * 64 + tcol * 4] = *(const float4*)&K[gbase];
            *(float4*)&Vs[j * 64 + tcol * 4] = *(const float4*)&V[gbase];
        }
        // mask words for this thread's query row: keys [m0, m0+64)
        const int w0 = m0 >> 5;
        uint32_t mw0 = Mbits[((size_t)(b * 128 + w0)) * 4096 + n];
        uint32_t mw1 = Mbits[((size_t)(b * 128 + w0 + 1)) * 4096 + n];
        __syncthreads();

        // --- 4 chunks of 16 keys ---
#pragma unroll
        for (int c0 = 0; c0 < 64; c0 += 16) {
            float s[16];
#pragma unroll
            for (int jj = 0; jj < 16; ++jj) {
                const float* kr = &Ks[(c0 + jj) * 64];
                float acc = 0.f;
#pragma unroll
                for (int d4 = 0; d4 < 16; ++d4) {
                    float4 kv = *(const float4*)(kr + d4 * 4);
                    acc = fmaf(q[4 * d4 + 0], kv.x, acc);
                    acc = fmaf(q[4 * d4 + 1], kv.y, acc);
                    acc = fmaf(q[4 * d4 + 2], kv.z, acc);
                    acc = fmaf(q[4 * d4 + 3], kv.w, acc);
                }
                s[jj] = acc;
            }
            // apply mask bits (chunk lies entirely within one 32-bit word)
            uint32_t mw = (c0 < 32) ? mw0 : mw1;
            int bit0 = c0 & 31;
#pragma unroll
            for (int jj = 0; jj < 16; ++jj) {
                if ((mw >> (bit0 + jj)) & 1u) s[jj] = -1e30f;
            }
            // chunk max + rescale
            float cm = s[0];
#pragma unroll
            for (int jj = 1; jj < 16; ++jj) cm = fmaxf(cm, s[jj]);
            float m_new = fmaxf(m, cm);
            float corr = __expf(m - m_new);
            l *= corr;
#pragma unroll
            for (int d = 0; d < 64; ++d) o[d] *= corr;
            m = m_new;
#pragma unroll
            for (int jj = 0; jj < 16; ++jj) {
                float p = (s[jj] < -1e29f) ? 0.f : __expf(s[jj] - m);
                l += p;
                const float* vr = &Vs[(c0 + jj) * 64];
#pragma unroll
                for (int d4 = 0; d4 < 16; ++d4) {
                    float4 vv = *(const float4*)(vr + d4 * 4);
                    o[4 * d4 + 0] = fmaf(p, vv.x, o[4 * d4 + 0]);
                    o[4 * d4 + 1] = fmaf(p, vv.y, o[4 * d4 + 1]);
                    o[4 * d4 + 2] = fmaf(p, vv.z, o[4 * d4 + 2]);
                    o[4 * d4 + 3] = fmaf(p, vv.w, o[4 * d4 + 3]);
                }
            }
        }
        __syncthreads();
    }

    float inv = 1.f / fmaxf(l, 1e-30f);
    float* op = &O[((size_t)(b * 4096 + n)) * 512 + h * 64];
#pragma unroll
    for (int d4 = 0; d4 < 16; ++d4) {
        float4 r;
        r.x = o[4 * d4 + 0] * inv;
        r.y = o[4 * d4 + 1] * inv;
        r.z = o[4 * d4 + 2] * inv;
        r.w = o[4 * d4 + 3] * inv;
        *(float4*)(op + d4 * 4) = r;
    }
}

// ---------------------------------------------------------------------------
// Launch
// ---------------------------------------------------------------------------
extern "C" void kernel_launch(void* const* d_in, const int* in_sizes, int n_in,
                              void* d_out, int out_size)
{
    const float* x       = (const float*)d_in[0];
    const float* context = (const float*)d_in[1];
    const int*   pos_x   = (const int*)d_in[2];
    const int*   pos_ctx = (const int*)d_in[3];
    const unsigned char* mask = (const unsigned char*)d_in[4];
    const float* Wq = (const float*)d_in[5];
    const float* bq = (const float*)d_in[6];
    const float* Wk = (const float*)d_in[7];
    const float* bk = (const float*)d_in[8];
    const float* Wv = (const float*)d_in[9];
    const float* bv = (const float*)d_in[10];
    const float* Wo = (const float*)d_in[11];
    const float* bo = (const float*)d_in[12];
    float* out = (float*)d_out;

    float *qp, *kp, *vp, *op;
    uint32_t* mb;
    cudaGetSymbolAddress((void**)&qp, g_Q);
    cudaGetSymbolAddress((void**)&kp, g_K);
    cudaGetSymbolAddress((void**)&vp, g_V);
    cudaGetSymbolAddress((void**)&op, g_O);
    cudaGetSymbolAddress((void**)&mb, g_Mbits);

    // mask canonicalization (dtype-robust)
    detect_mask_kernel<<<1, 256>>>((const uint32_t*)mask);
    pack_mask_kernel<<<BATCH * SEQ_N, 128>>>(mask, mb);

    dim3 ggrid(512 / 64, (BATCH * SEQ_N) / 128);   // (8, 64)

    gemm512_kernel<<<ggrid, 256>>>(x, Wq, bq, qp);
    gemm512_kernel<<<ggrid, 256>>>(context, Wk, bk, kp);
    gemm512_kernel<<<ggrid, 256>>>(context, Wv, bv, vp);

    const int rope_total = BATCH * SEQ_N * HEADS * 32;   // 2,097,152
    const float qscale = 0.125f;                          // hd^{-1/2}
    rope2d_kernel<<<(rope_total + 255) / 256, 256>>>(qp, pos_x, qscale, rope_total);
    rope2d_kernel<<<(rope_total + 255) / 256, 256>>>(kp, pos_ctx, 1.0f, rope_total);

    dim3 agrid(SEQ_N / 128, HEADS, BATCH);   // (32, 8, 2)
    attn_kernel<<<agrid, 128>>>(qp, kp, vp, mb, op);

    gemm512_kernel<<<ggrid, 256>>>(op, Wo, bo, out);
}

// round 3
// speedup vs baseline: 4.6898x; 4.6898x over previous
#include <cuda_runtime.h>
#include <cuda_fp16.h>
#include <cstdint>

#define BATCH 2
#define SEQ_N 4096
#define SEQ_M 4096
#define DIM_C 512
#define HEADS 8
#define HDIM  64

// ---------------------------------------------------------------------------
// Scratch
// ---------------------------------------------------------------------------
__device__ float g_Q[BATCH * SEQ_N * DIM_C];
__device__ float g_K[BATCH * SEQ_M * DIM_C];
__device__ float g_V[BATCH * SEQ_M * DIM_C];
__device__ float g_O[BATCH * SEQ_N * DIM_C];
__device__ __half g_Qh[BATCH * HEADS * SEQ_N * HDIM];   // [b][h][n][64], rope+scale applied
__device__ __half g_Kh[BATCH * HEADS * SEQ_M * HDIM];   // [b][h][m][64], rope applied
__device__ __half g_Vt[BATCH * HEADS * HDIM * SEQ_M];   // [b][h][d][m]  (transposed)
__device__ uint32_t g_Mbits[BATCH * 128 * SEQ_N];       // transposed packed mask
__device__ int g_maskBool;

// ---------------------------------------------------------------------------
// helpers
// ---------------------------------------------------------------------------
__device__ __forceinline__ float ex2f(float x) {
    float y; asm("ex2.approx.ftz.f32 %0, %1;" : "=f"(y) : "f"(x)); return y;
}
__device__ __forceinline__ uint32_t pack_h2(float lo, float hi) {
    uint32_t r; asm("cvt.rn.f16x2.f32 %0, %1, %2;" : "=r"(r) : "f"(hi), "f"(lo)); return r;
}
__device__ __forceinline__ void mma_f16(float c[4], const uint32_t a[4],
                                        uint32_t b0, uint32_t b1) {
    asm volatile(
        "mma.sync.aligned.m16n8k16.row.col.f32.f16.f16.f32 "
        "{%0,%1,%2,%3}, {%4,%5,%6,%7}, {%8,%9}, {%0,%1,%2,%3};"
        : "+f"(c[0]), "+f"(c[1]), "+f"(c[2]), "+f"(c[3])
        : "r"(a[0]), "r"(a[1]), "r"(a[2]), "r"(a[3]), "r"(b0), "r"(b1));
}

// ---------------------------------------------------------------------------
// Mask dtype detection + packing (unchanged, verified round 2)
// ---------------------------------------------------------------------------
__global__ void detect_mask_kernel(const uint32_t* __restrict__ m)
{
    __shared__ int found;
    if (threadIdx.x == 0) found = 0;
    __syncthreads();
    uint32_t v = m[threadIdx.x] | m[threadIdx.x + 256] |
                 m[threadIdx.x + 512] | m[threadIdx.x + 768];
    if (v > 1u) atomicOr(&found, 1);
    __syncthreads();
    if (threadIdx.x == 0) g_maskBool = found;
}

__global__ __launch_bounds__(128) void pack_mask_kernel(
    const unsigned char* __restrict__ mraw, uint32_t* __restrict__ out)
{
    const int bn = blockIdx.x;
    const int w  = threadIdx.x;
    const int b  = bn >> 12;
    const int n  = bn & 4095;
    uint32_t bits = 0;
    if (g_maskBool) {
        const uint32_t* p = (const uint32_t*)(mraw + (size_t)bn * 4096) + w * 8;
#pragma unroll
        for (int i = 0; i < 8; ++i) {
            uint32_t v = p[i];
#pragma unroll
            for (int j = 0; j < 4; ++j)
                if ((v >> (j * 8)) & 0xFFu) bits |= 1u << (i * 4 + j);
        }
    } else {
        const int* p = (const int*)mraw + (size_t)bn * 4096 + w * 32;
#pragma unroll
        for (int i = 0; i < 32; ++i)
            if (p[i] != 0) bits |= 1u << i;
    }
    out[((size_t)(b * 128 + w)) * 4096 + n] = bits;
}

// ---------------------------------------------------------------------------
// SGEMM (fp32) — unchanged from round 2 (verified)
// ---------------------------------------------------------------------------
__global__ __launch_bounds__(256) void gemm512_kernel(
    const float* __restrict__ A, const float* __restrict__ W,
    const float* __restrict__ bias, float* __restrict__ Y)
{
    const int BM = 128, BN = 64, BK = 16;
    __shared__ __align__(16) float As[BK][BM];
    __shared__ __align__(16) float Bs[BK][BN];

    const int tid = threadIdx.x;
    const int tx = tid & 15, ty = tid >> 4;
    const int row0 = blockIdx.y * BM, col0 = blockIdx.x * BN;

    float acc[8][4];
#pragma unroll
    for (int i = 0; i < 8; ++i)
#pragma unroll
        for (int j = 0; j < 4; ++j) acc[i][j] = 0.f;

    const int am = tid >> 2, ak = (tid & 3) * 4;
    const int br = tid >> 4, bc = (tid & 15) * 4;

    for (int k0 = 0; k0 < 512; k0 += BK) {
        float4 a0 = *(const float4*)&A[(size_t)(row0 + am) * 512 + k0 + ak];
        float4 a1 = *(const float4*)&A[(size_t)(row0 + am + 64) * 512 + k0 + ak];
        As[ak + 0][am] = a0.x; As[ak + 1][am] = a0.y;
        As[ak + 2][am] = a0.z; As[ak + 3][am] = a0.w;
        As[ak + 0][am + 64] = a1.x; As[ak + 1][am + 64] = a1.y;
        As[ak + 2][am + 64] = a1.z; As[ak + 3][am + 64] = a1.w;
        float4 w4 = *(const float4*)&W[(size_t)(k0 + br) * 512 + col0 + bc];
        *(float4*)&Bs[br][bc] = w4;
        __syncthreads();

#pragma unroll
        for (int k = 0; k < BK; ++k) {
            float af[8], bf[4];
            float4 afa = *(const float4*)&As[k][ty * 8];
            float4 afb = *(const float4*)&As[k][ty * 8 + 4];
            af[0] = afa.x; af[1] = afa.y; af[2] = afa.z; af[3] = afa.w;
            af[4] = afb.x; af[5] = afb.y; af[6] = afb.z; af[7] = afb.w;
            float4 bfv = *(const float4*)&Bs[k][tx * 4];
            bf[0] = bfv.x; bf[1] = bfv.y; bf[2] = bfv.z; bf[3] = bfv.w;
#pragma unroll
            for (int i = 0; i < 8; ++i)
#pragma unroll
                for (int j = 0; j < 4; ++j)
                    acc[i][j] = fmaf(af[i], bf[j], acc[i][j]);
        }
        __syncthreads();
    }

    float4 bia = *(const float4*)&bias[col0 + tx * 4];
#pragma unroll
    for (int i = 0; i < 8; ++i) {
        float4 r;
        r.x = acc[i][0] + bia.x; r.y = acc[i][1] + bia.y;
        r.z = acc[i][2] + bia.z; r.w = acc[i][3] + bia.w;
        *(float4*)&Y[(size_t)(row0 + ty * 8 + i) * 512 + col0 + tx * 4] = r;
    }
}

// ---------------------------------------------------------------------------
// RoPE 2D: read fp32 [b,n,h,64], write fp16 [b,h,n,64] with scale folded in.
// Q gets 0.125 * log2(e) so attention softmax can run in exp2 space.
// ---------------------------------------------------------------------------
__global__ void rope2d_h_kernel(const float* __restrict__ src, __half* __restrict__ dst,
                                const int* __restrict__ pos, float qscale, int total)
{
    int idx = blockIdx.x * blockDim.x + threadIdx.x;
    if (idx >= total) return;
    int pair = idx & 31;
    int h    = (idx >> 5) & 7;
    int n    = (idx >> 8) & 4095;
    int b    = idx >> 20;
    int blk  = pair >> 4;
    int ii   = pair & 15;

    float invf = exp2f(-(float)ii * 0.41524101186092864f);   // 100^{-ii/16}
    int p = pos[((size_t)(b * 4096 + n)) * 2 + blk];
    float ang = (float)p * invf;
    float sn, cs;
    sincosf(ang, &sn, &cs);

    size_t sbase = ((size_t)(b * 4096 + n) * 8 + h) * 64 + blk * 32 + ii;
    float v1 = src[sbase];
    float v2 = src[sbase + 16];
    size_t dbase = ((size_t)((b * 8 + h) * 4096 + n)) * 64 + blk * 32 + ii;
    dst[dbase]      = __float2half((v1 * cs - v2 * sn) * qscale);
    dst[dbase + 16] = __float2half((v2 * cs + v1 * sn) * qscale);
}

// ---------------------------------------------------------------------------
// V: fp32 [b,m,(h,d)] -> fp16 transposed [b,h,d,m] (tiled via smem)
// ---------------------------------------------------------------------------
__global__ __launch_bounds__(256) void vtrans_kernel(
    const float* __restrict__ V, uint32_t* __restrict__ Vt)
{
    const int m0 = blockIdx.x * 64;
    const int h  = blockIdx.y;
    const int b  = blockIdx.z;
    const int t  = threadIdx.x;
    __shared__ float S[64][65];
#pragma unroll
    for (int i = 0; i < 16; ++i) {
        int e = i * 256 + t;
        int m = e >> 6, d = e & 63;
        S[m][d] = V[((size_t)(b * 4096 + m0 + m)) * 512 + h * 64 + d];
    }
    __syncthreads();
#pragma unroll
    for (int i = 0; i < 8; ++i) {
        int e = i * 256 + t;
        int d = e >> 5, mm = e & 31;
        uint32_t v = pack_h2(S[2 * mm][d], S[2 * mm + 1][d]);
        Vt[((size_t)((b * 8 + h) * 64 + d)) * 2048 + (m0 >> 1) + mm] = v;
    }
}

// ---------------------------------------------------------------------------
// Flash attention, fp16 mma.sync.m16n8k16, fp32 accum, online softmax (exp2).
// 256 thr = 8 warps; warp w owns q rows [q0+16w, q0+16w+16); key tiles of 64.
// ---------------------------------------------------------------------------
__global__ __launch_bounds__(256) void attn_mma_kernel(
    const uint32_t* __restrict__ Qh, const uint32_t* __restrict__ Kh,
    const uint32_t* __restrict__ Vt, const uint32_t* __restrict__ Mb,
    float* __restrict__ O)
{
    const int b = blockIdx.z, h = blockIdx.y;
    const int q0 = blockIdx.x * 128;
    const int t = threadIdx.x, w = t >> 5, lane = t & 31;
    const int qr = lane >> 2, qc = lane & 3;

    __shared__ uint32_t Ks[64 * 36];   // K tile [key][dim], pitch 36 words
    __shared__ uint32_t Vs[64 * 36];   // V tile [dim][key], pitch 36 words

    const size_t bh = (size_t)(b * 8 + h);
    const int n0 = q0 + w * 16 + qr;
    const int n1 = n0 + 8;

    // Q fragments (A, m16k16 x 4 chunks over d=64)
    uint32_t qa[4][4];
    {
        const uint32_t* Qb = Qh + (bh * 4096 + q0 + (size_t)w * 16) * 32;
#pragma unroll
        for (int kc = 0; kc < 4; ++kc) {
            qa[kc][0] = Qb[qr * 32 + kc * 8 + qc];
            qa[kc][1] = Qb[(qr + 8) * 32 + kc * 8 + qc];
            qa[kc][2] = Qb[qr * 32 + kc * 8 + qc + 4];
            qa[kc][3] = Qb[(qr + 8) * 32 + kc * 8 + qc + 4];
        }
    }

    float o[8][4];
#pragma unroll
    for (int j = 0; j < 8; ++j)
#pragma unroll
        for (int k = 0; k < 4; ++k) o[j][k] = 0.f;
    float m0r = -1e30f, m1r = -1e30f, l0 = 0.f, l1 = 0.f;

    const uint32_t* Kg = Kh + bh * SEQ_M * 32;
    const uint32_t* Vg = Vt + bh * HDIM * 2048;

    for (int mt = 0; mt < SEQ_M / 64; ++mt) {
        const int mk = mt * 64;
        // cooperative tile loads (2048 words each)
#pragma unroll
        for (int i = 0; i < 8; ++i) {
            int e = i * 256 + t;
            int row = e >> 5, col = e & 31;
            Ks[row * 36 + col] = Kg[(size_t)(mk + row) * 32 + col];
            Vs[row * 36 + col] = Vg[(size_t)row * 2048 + (mk >> 1) + col];
        }
        const int wz = mk >> 5;
        uint32_t ma0 = Mb[((size_t)(b * 128 + wz)) * 4096 + n0];
        uint32_t ma1 = Mb[((size_t)(b * 128 + wz + 1)) * 4096 + n0];
        uint32_t mb0 = Mb[((size_t)(b * 128 + wz)) * 4096 + n1];
        uint32_t mb1 = Mb[((size_t)(b * 128 + wz + 1)) * 4096 + n1];
        __syncthreads();

        // ---- scores: S = Q Kt (16 x 64 per warp) ----
        float c[8][4];
#pragma unroll
        for (int j = 0; j < 8; ++j) {
            c[j][0] = c[j][1] = c[j][2] = c[j][3] = 0.f;
#pragma unroll
            for (int kc = 0; kc < 4; ++kc) {
                uint32_t b0 = Ks[(j * 8 + qr) * 36 + kc * 8 + qc];
                uint32_t b1 = Ks[(j * 8 + qr) * 36 + kc * 8 + qc + 4];
                mma_f16(c[j], qa[kc], b0, b1);
            }
        }
        // ---- mask + row max ----
        float rx0 = -1e30f, rx1 = -1e30f;
#pragma unroll
        for (int j = 0; j < 8; ++j) {
            int bi = j * 8 + qc * 2;
            uint32_t w0 = (bi < 32) ? ma0 : ma1;
            uint32_t w1 = (bi < 32) ? mb0 : mb1;
            int sh = bi & 31;
            if ((w0 >> sh) & 1u)       c[j][0] = -1e30f;
            if ((w0 >> (sh + 1)) & 1u) c[j][1] = -1e30f;
            if ((w1 >> sh) & 1u)       c[j][2] = -1e30f;
            if ((w1 >> (sh + 1)) & 1u) c[j][3] = -1e30f;
            rx0 = fmaxf(rx0, fmaxf(c[j][0], c[j][1]));
            rx1 = fmaxf(rx1, fmaxf(c[j][2], c[j][3]));
        }
        rx0 = fmaxf(rx0, __shfl_xor_sync(0xffffffffu, rx0, 1));
        rx0 = fmaxf(rx0, __shfl_xor_sync(0xffffffffu, rx0, 2));
        rx1 = fmaxf(rx1, __shfl_xor_sync(0xffffffffu, rx1, 1));
        rx1 = fmaxf(rx1, __shfl_xor_sync(0xffffffffu, rx1, 2));
        float mn0 = fmaxf(m0r, rx0), mn1 = fmaxf(m1r, rx1);
        float cr0 = ex2f(m0r - mn0), cr1 = ex2f(m1r - mn1);
        m0r = mn0; m1r = mn1;
        l0 *= cr0; l1 *= cr1;
#pragma unroll
        for (int j = 0; j < 8; ++j) {
            o[j][0] *= cr0; o[j][1] *= cr0; o[j][2] *= cr1; o[j][3] *= cr1;
        }
        // ---- p = exp2(s - m); masked -1e30 flushes to 0 via ftz ----
#pragma unroll
        for (int j = 0; j < 8; ++j) {
            c[j][0] = ex2f(c[j][0] - m0r); c[j][1] = ex2f(c[j][1] - m0r);
            c[j][2] = ex2f(c[j][2] - m1r); c[j][3] = ex2f(c[j][3] - m1r);
            l0 += c[j][0] + c[j][1];
            l1 += c[j][2] + c[j][3];
        }
        // ---- O += P V ----
#pragma unroll
        for (int kc = 0; kc < 4; ++kc) {
            uint32_t pa[4];
            pa[0] = pack_h2(c[2 * kc][0], c[2 * kc][1]);
            pa[1] = pack_h2(c[2 * kc][2], c[2 * kc][3]);
            pa[2] = pack_h2(c[2 * kc + 1][0], c[2 * kc + 1][1]);
            pa[3] = pack_h2(c[2 * kc + 1][2], c[2 * kc + 1][3]);
#pragma unroll
            for (int nd = 0; nd < 8; ++nd) {
                uint32_t b0 = Vs[(nd * 8 + qr) * 36 + kc * 8 + qc];
                uint32_t b1 = Vs[(nd * 8 + qr) * 36 + kc * 8 + qc + 4];
                mma_f16(o[nd], pa, b0, b1);
            }
        }
        __syncthreads();
    }

    l0 += __shfl_xor_sync(0xffffffffu, l0, 1);
    l0 += __shfl_xor_sync(0xffffffffu, l0, 2);
    l1 += __shfl_xor_sync(0xffffffffu, l1, 1);
    l1 += __shfl_xor_sync(0xffffffffu, l1, 2);
    float i0 = 1.f / fmaxf(l0, 1e-30f);
    float i1 = 1.f / fmaxf(l1, 1e-30f);
#pragma unroll
    for (int j = 0; j < 8; ++j) {
        int d = j * 8 + qc * 2;
        float2 v0 = make_float2(o[j][0] * i0, o[j][1] * i0);
        float2 v1 = make_float2(o[j][2] * i1, o[j][3] * i1);
        *(float2*)&O[((size_t)(b * 4096 + n0)) * 512 + h * 64 + d] = v0;
        *(float2*)&O[((size_t)(b * 4096 + n1)) * 512 + h * 64 + d] = v1;
    }
}

// ---------------------------------------------------------------------------
// Launch
// ---------------------------------------------------------------------------
extern "C" void kernel_launch(void* const* d_in, const int* in_sizes, int n_in,
                              void* d_out, int out_size)
{
    const float* x       = (const float*)d_in[0];
    const float* context = (const float*)d_in[1];
    const int*   pos_x   = (const int*)d_in[2];
    const int*   pos_ctx = (const int*)d_in[3];
    const unsigned char* mask = (const unsigned char*)d_in[4];
    const float* Wq = (const float*)d_in[5];
    const float* bq = (const float*)d_in[6];
    const float* Wk = (const float*)d_in[7];
    const float* bk = (const float*)d_in[8];
    const float* Wv = (const float*)d_in[9];
    const float* bv = (const float*)d_in[10];
    const float* Wo = (const float*)d_in[11];
    const float* bo = (const float*)d_in[12];
    float* out = (float*)d_out;

    float *qp, *kp, *vp, *op;
    __half *qh, *kh;
    uint32_t *vt, *mb;
    cudaGetSymbolAddress((void**)&qp, g_Q);
    cudaGetSymbolAddress((void**)&kp, g_K);
    cudaGetSymbolAddress((void**)&vp, g_V);
    cudaGetSymbolAddress((void**)&op, g_O);
    cudaGetSymbolAddress((void**)&qh, g_Qh);
    cudaGetSymbolAddress((void**)&kh, g_Kh);
    cudaGetSymbolAddress((void**)&vt, g_Vt);
    cudaGetSymbolAddress((void**)&mb, g_Mbits);

    detect_mask_kernel<<<1, 256>>>((const uint32_t*)mask);
    pack_mask_kernel<<<BATCH * SEQ_N, 128>>>(mask, mb);

    dim3 ggrid(512 / 64, (BATCH * SEQ_N) / 128);

    gemm512_kernel<<<ggrid, 256>>>(x, Wq, bq, qp);
    gemm512_kernel<<<ggrid, 256>>>(context, Wk, bk, kp);
    gemm512_kernel<<<ggrid, 256>>>(context, Wv, bv, vp);

    const int rope_total = BATCH * SEQ_N * HEADS * 32;
    const float qscale = 0.125f * 1.4426950408889634f;   // hd^-1/2 * log2(e)
    rope2d_h_kernel<<<(rope_total + 255) / 256, 256>>>(qp, qh, pos_x, qscale, rope_total);
    rope2d_h_kernel<<<(rope_total + 255) / 256, 256>>>(kp, kh, pos_ctx, 1.0f, rope_total);

    dim3 vgrid(SEQ_M / 64, HEADS, BATCH);
    vtrans_kernel<<<vgrid, 256>>>(vp, vt);

    dim3 agrid(SEQ_N / 128, HEADS, BATCH);
    attn_mma_kernel<<<agrid, 256>>>((const uint32_t*)qh, (const uint32_t*)kh,
                                    vt, mb, op);

    gemm512_kernel<<<ggrid, 256>>>(op, Wo, bo, out);
}

// round 4
// speedup vs baseline: 5.7755x; 1.2315x over previous
#include <cuda_runtime.h>
#include <cuda_fp16.h>
#include <cstdint>

#define BATCH 2
#define SEQ_N 4096
#define SEQ_M 4096
#define DIM_C 512
#define HEADS 8
#define HDIM  64

// ---------------------------------------------------------------------------
// Scratch
// ---------------------------------------------------------------------------
__device__ float g_Q[BATCH * SEQ_N * DIM_C];
__device__ float g_K[BATCH * SEQ_M * DIM_C];
__device__ float g_V[BATCH * SEQ_M * DIM_C];
__device__ float g_O[BATCH * SEQ_N * DIM_C];
__device__ __half g_Qh[BATCH * HEADS * SEQ_N * HDIM];
__device__ __half g_Kh[BATCH * HEADS * SEQ_M * HDIM];
__device__ __half g_Vt[BATCH * HEADS * HDIM * SEQ_M];
__device__ uint32_t g_Mbits[BATCH * 128 * SEQ_N];
__device__ int g_maskBool;
// fp16-split GEMM operands
__device__ __half g_Xh[BATCH * SEQ_N * DIM_C];
__device__ __half g_Xl[BATCH * SEQ_N * DIM_C];
__device__ __half g_Ch[BATCH * SEQ_M * DIM_C];
__device__ __half g_Cl[BATCH * SEQ_M * DIM_C];
__device__ __half g_Wth[4 * DIM_C * DIM_C];   // transposed [n][k], 4 weights
__device__ __half g_Wtl[4 * DIM_C * DIM_C];

// ---------------------------------------------------------------------------
// helpers
// ---------------------------------------------------------------------------
__device__ __forceinline__ float ex2f(float x) {
    float y; asm("ex2.approx.ftz.f32 %0, %1;" : "=f"(y) : "f"(x)); return y;
}
__device__ __forceinline__ uint32_t pack_h2(float lo, float hi) {
    uint32_t r; asm("cvt.rn.f16x2.f32 %0, %1, %2;" : "=r"(r) : "f"(hi), "f"(lo)); return r;
}
__device__ __forceinline__ void mma_f16(float c[4], const uint32_t a[4],
                                        uint32_t b0, uint32_t b1) {
    asm volatile(
        "mma.sync.aligned.m16n8k16.row.col.f32.f16.f16.f32 "
        "{%0,%1,%2,%3}, {%4,%5,%6,%7}, {%8,%9}, {%0,%1,%2,%3};"
        : "+f"(c[0]), "+f"(c[1]), "+f"(c[2]), "+f"(c[3])
        : "r"(a[0]), "r"(a[1]), "r"(a[2]), "r"(a[3]), "r"(b0), "r"(b1));
}

// ---------------------------------------------------------------------------
// Mask dtype detection + packing (verified)
// ---------------------------------------------------------------------------
__global__ void detect_mask_kernel(const uint32_t* __restrict__ m)
{
    __shared__ int found;
    if (threadIdx.x == 0) found = 0;
    __syncthreads();
    uint32_t v = m[threadIdx.x] | m[threadIdx.x + 256] |
                 m[threadIdx.x + 512] | m[threadIdx.x + 768];
    if (v > 1u) atomicOr(&found, 1);
    __syncthreads();
    if (threadIdx.x == 0) g_maskBool = found;
}

__global__ __launch_bounds__(128) void pack_mask_kernel(
    const unsigned char* __restrict__ mraw, uint32_t* __restrict__ out)
{
    const int bn = blockIdx.x;
    const int w  = threadIdx.x;
    const int b  = bn >> 12;
    const int n  = bn & 4095;
    uint32_t bits = 0;
    if (g_maskBool) {
        const uint32_t* p = (const uint32_t*)(mraw + (size_t)bn * 4096) + w * 8;
#pragma unroll
        for (int i = 0; i < 8; ++i) {
            uint32_t v = p[i];
#pragma unroll
            for (int j = 0; j < 4; ++j)
                if ((v >> (j * 8)) & 0xFFu) bits |= 1u << (i * 4 + j);
        }
    } else {
        const int* p = (const int*)mraw + (size_t)bn * 4096 + w * 32;
#pragma unroll
        for (int i = 0; i < 32; ++i)
            if (p[i] != 0) bits |= 1u << i;
    }
    out[((size_t)(b * 128 + w)) * 4096 + n] = bits;
}

// ---------------------------------------------------------------------------
// fp16 split of an fp32 matrix (element-wise): hi = rte16(v), lo = rte16(v-hi)
// ---------------------------------------------------------------------------
__global__ void split_kernel(const float4* __restrict__ src,
                             uint2* __restrict__ hi, uint2* __restrict__ lo, int n4)
{
    int i = blockIdx.x * blockDim.x + threadIdx.x;
    if (i >= n4) return;
    float4 v = src[i];
    __half hx = __float2half(v.x), hy = __float2half(v.y);
    __half hz = __float2half(v.z), hw = __float2half(v.w);
    float rx = v.x - __half2float(hx), ry = v.y - __half2float(hy);
    float rz = v.z - __half2float(hz), rw = v.w - __half2float(hw);
    uint2 h, l;
    h.x = __half2half2(hx).x; // placeholder avoided; pack below
    h.x = ((uint32_t)__half_as_ushort(hy) << 16) | __half_as_ushort(hx);
    h.y = ((uint32_t)__half_as_ushort(hw) << 16) | __half_as_ushort(hz);
    l.x = pack_h2(rx, ry);
    l.y = pack_h2(rz, rw);
    hi[i] = h;
    lo[i] = l;
}

// ---------------------------------------------------------------------------
// Weight transpose + split: W[k][n] fp32 -> Wt_hi/lo[n][k] fp16 (as h2 words)
// grid (8,8) of 64x64 tiles, 256 threads
// ---------------------------------------------------------------------------
__global__ __launch_bounds__(256) void wsplit_kernel(
    const float* __restrict__ W, uint32_t* __restrict__ Wth, uint32_t* __restrict__ Wtl)
{
    const int n0 = blockIdx.x * 64;
    const int k0 = blockIdx.y * 64;
    const int t  = threadIdx.x;
    __shared__ float S[64][65];
#pragma unroll
    for (int i = 0; i < 16; ++i) {
        int e = i * 256 + t;
        int r = e >> 6, c = e & 63;             // r = k offset, c = n offset
        S[r][c] = W[(size_t)(k0 + r) * 512 + n0 + c];
    }
    __syncthreads();
#pragma unroll
    for (int i = 0; i < 8; ++i) {
        int e = i * 256 + t;
        int n = e >> 5, kw = e & 31;
        float v0 = S[2 * kw][n], v1 = S[2 * kw + 1][n];
        __half h0 = __float2half(v0), h1 = __float2half(v1);
        float r0 = v0 - __half2float(h0), r1 = v1 - __half2float(h1);
        size_t dst = (size_t)(n0 + n) * 256 + (k0 >> 1) + kw;
        Wth[dst] = ((uint32_t)__half_as_ushort(h1) << 16) | __half_as_ushort(h0);
        Wtl[dst] = pack_h2(r0, r1);
    }
}

// ---------------------------------------------------------------------------
// Tensor-core GEMM with fp16 split (3-product): Y = A@W + bias, fp32 out.
// A (hi/lo): [8192][512] fp16 (256 h2 words/row). Wt (hi/lo): [512 n][512 k].
// Block 128x64, BK=32, 256 thr = 8 warps, warp tile 32x32.
// ---------------------------------------------------------------------------
__global__ __launch_bounds__(256) void gemm_mma_kernel(
    const uint32_t* __restrict__ Ah, const uint32_t* __restrict__ Al,
    const uint32_t* __restrict__ Wth, const uint32_t* __restrict__ Wtl,
    const float* __restrict__ bias, float* __restrict__ Y)
{
    const int row0 = blockIdx.y * 128;
    const int col0 = blockIdx.x * 64;
    const int t = threadIdx.x, w = t >> 5, lane = t & 31;
    const int wm = w & 3, wn = w >> 2;
    const int qr = lane >> 2, qc = lane & 3;

    __shared__ uint32_t Ahs[128 * 20];
    __shared__ uint32_t Als[128 * 20];
    __shared__ uint32_t Whs[64 * 20];
    __shared__ uint32_t Wls[64 * 20];

    float acc[2][4][4];
#pragma unroll
    for (int mt = 0; mt < 2; ++mt)
#pragma unroll
        for (int nt = 0; nt < 4; ++nt)
#pragma unroll
            for (int k = 0; k < 4; ++k) acc[mt][nt][k] = 0.f;

    for (int ch = 0; ch < 16; ++ch) {
        const int kw = ch * 16;
        // A tiles: 128 rows x 16 words each (hi, lo)
#pragma unroll
        for (int i = 0; i < 2; ++i) {
            int idx = i * 256 + t;
            int r = idx >> 2, c4 = (idx & 3) * 4;
            *(uint4*)&Ahs[r * 20 + c4] =
                *(const uint4*)&Ah[(size_t)(row0 + r) * 256 + kw + c4];
            *(uint4*)&Als[r * 20 + c4] =
                *(const uint4*)&Al[(size_t)(row0 + r) * 256 + kw + c4];
        }
        // W tiles: 64 rows x 16 words
        {
            int r = t >> 2, c4 = (t & 3) * 4;
            *(uint4*)&Whs[r * 20 + c4] =
                *(const uint4*)&Wth[(size_t)(col0 + r) * 256 + kw + c4];
            *(uint4*)&Wls[r * 20 + c4] =
                *(const uint4*)&Wtl[(size_t)(col0 + r) * 256 + kw + c4];
        }
        __syncthreads();

#pragma unroll
        for (int kc = 0; kc < 2; ++kc) {
            uint32_t ah[2][4], al[2][4];
#pragma unroll
            for (int mt = 0; mt < 2; ++mt) {
                int rb = (wm * 32 + mt * 16 + qr) * 20 + kc * 8 + qc;
                ah[mt][0] = Ahs[rb];           ah[mt][1] = Ahs[rb + 8 * 20];
                ah[mt][2] = Ahs[rb + 4];       ah[mt][3] = Ahs[rb + 8 * 20 + 4];
                al[mt][0] = Als[rb];           al[mt][1] = Als[rb + 8 * 20];
                al[mt][2] = Als[rb + 4];       al[mt][3] = Als[rb + 8 * 20 + 4];
            }
            uint32_t bh[4][2], bl[4][2];
#pragma unroll
            for (int nt = 0; nt < 4; ++nt) {
                int rb = (wn * 32 + nt * 8 + qr) * 20 + kc * 8 + qc;
                bh[nt][0] = Whs[rb]; bh[nt][1] = Whs[rb + 4];
                bl[nt][0] = Wls[rb]; bl[nt][1] = Wls[rb + 4];
            }
#pragma unroll
            for (int mt = 0; mt < 2; ++mt)
#pragma unroll
                for (int nt = 0; nt < 4; ++nt) {
                    mma_f16(acc[mt][nt], ah[mt], bh[nt][0], bh[nt][1]);
                    mma_f16(acc[mt][nt], al[mt], bh[nt][0], bh[nt][1]);
                    mma_f16(acc[mt][nt], ah[mt], bl[nt][0], bl[nt][1]);
                }
        }
        __syncthreads();
    }

#pragma unroll
    for (int mt = 0; mt < 2; ++mt)
#pragma unroll
        for (int nt = 0; nt < 4; ++nt) {
            int row = row0 + wm * 32 + mt * 16 + qr;
            int col = col0 + wn * 32 + nt * 8 + qc * 2;
            float2 bi = *(const float2*)&bias[col];
            float2 v0 = make_float2(acc[mt][nt][0] + bi.x, acc[mt][nt][1] + bi.y);
            float2 v1 = make_float2(acc[mt][nt][2] + bi.x, acc[mt][nt][3] + bi.y);
            *(float2*)&Y[(size_t)row * 512 + col] = v0;
            *(float2*)&Y[(size_t)(row + 8) * 512 + col] = v1;
        }
}

// ---------------------------------------------------------------------------
// RoPE 2D: fp32 [b,n,h,64] -> fp16 [b,h,n,64], scale folded in.
// ---------------------------------------------------------------------------
__global__ void rope2d_h_kernel(const float* __restrict__ src, __half* __restrict__ dst,
                                const int* __restrict__ pos, float qscale, int total)
{
    int idx = blockIdx.x * blockDim.x + threadIdx.x;
    if (idx >= total) return;
    int pair = idx & 31;
    int h    = (idx >> 5) & 7;
    int n    = (idx >> 8) & 4095;
    int b    = idx >> 20;
    int blk  = pair >> 4;
    int ii   = pair & 15;

    float invf = exp2f(-(float)ii * 0.41524101186092864f);
    int p = pos[((size_t)(b * 4096 + n)) * 2 + blk];
    float ang = (float)p * invf;
    float sn, cs;
    sincosf(ang, &sn, &cs);

    size_t sbase = ((size_t)(b * 4096 + n) * 8 + h) * 64 + blk * 32 + ii;
    float v1 = src[sbase];
    float v2 = src[sbase + 16];
    size_t dbase = ((size_t)((b * 8 + h) * 4096 + n)) * 64 + blk * 32 + ii;
    dst[dbase]      = __float2half((v1 * cs - v2 * sn) * qscale);
    dst[dbase + 16] = __float2half((v2 * cs + v1 * sn) * qscale);
}

// ---------------------------------------------------------------------------
// V: fp32 [b,m,(h,d)] -> fp16 transposed [b,h,d,m]
// ---------------------------------------------------------------------------
__global__ __launch_bounds__(256) void vtrans_kernel(
    const float* __restrict__ V, uint32_t* __restrict__ Vt)
{
    const int m0 = blockIdx.x * 64;
    const int h  = blockIdx.y;
    const int b  = blockIdx.z;
    const int t  = threadIdx.x;
    __shared__ float S[64][65];
#pragma unroll
    for (int i = 0; i < 16; ++i) {
        int e = i * 256 + t;
        int m = e >> 6, d = e & 63;
        S[m][d] = V[((size_t)(b * 4096 + m0 + m)) * 512 + h * 64 + d];
    }
    __syncthreads();
#pragma unroll
    for (int i = 0; i < 8; ++i) {
        int e = i * 256 + t;
        int d = e >> 5, mm = e & 31;
        uint32_t v = pack_h2(S[2 * mm][d], S[2 * mm + 1][d]);
        Vt[((size_t)((b * 8 + h) * 64 + d)) * 2048 + (m0 >> 1) + mm] = v;
    }
}

// ---------------------------------------------------------------------------
// Flash attention (verified round 3)
// ---------------------------------------------------------------------------
__global__ __launch_bounds__(256) void attn_mma_kernel(
    const uint32_t* __restrict__ Qh, const uint32_t* __restrict__ Kh,
    const uint32_t* __restrict__ Vt, const uint32_t* __restrict__ Mb,
    float* __restrict__ O)
{
    const int b = blockIdx.z, h = blockIdx.y;
    const int q0 = blockIdx.x * 128;
    const int t = threadIdx.x, w = t >> 5, lane = t & 31;
    const int qr = lane >> 2, qc = lane & 3;

    __shared__ uint32_t Ks[64 * 36];
    __shared__ uint32_t Vs[64 * 36];

    const size_t bh = (size_t)(b * 8 + h);
    const int n0 = q0 + w * 16 + qr;
    const int n1 = n0 + 8;

    uint32_t qa[4][4];
    {
        const uint32_t* Qb = Qh + (bh * 4096 + q0 + (size_t)w * 16) * 32;
#pragma unroll
        for (int kc = 0; kc < 4; ++kc) {
            qa[kc][0] = Qb[qr * 32 + kc * 8 + qc];
            qa[kc][1] = Qb[(qr + 8) * 32 + kc * 8 + qc];
            qa[kc][2] = Qb[qr * 32 + kc * 8 + qc + 4];
            qa[kc][3] = Qb[(qr + 8) * 32 + kc * 8 + qc + 4];
        }
    }

    float o[8][4];
#pragma unroll
    for (int j = 0; j < 8; ++j)
#pragma unroll
        for (int k = 0; k < 4; ++k) o[j][k] = 0.f;
    float m0r = -1e30f, m1r = -1e30f, l0 = 0.f, l1 = 0.f;

    const uint32_t* Kg = Kh + bh * SEQ_M * 32;
    const uint32_t* Vg = Vt + bh * HDIM * 2048;

    for (int mt = 0; mt < SEQ_M / 64; ++mt) {
        const int mk = mt * 64;
#pragma unroll
        for (int i = 0; i < 8; ++i) {
            int e = i * 256 + t;
            int row = e >> 5, col = e & 31;
            Ks[row * 36 + col] = Kg[(size_t)(mk + row) * 32 + col];
            Vs[row * 36 + col] = Vg[(size_t)row * 2048 + (mk >> 1) + col];
        }
        const int wz = mk >> 5;
        uint32_t ma0 = Mb[((size_t)(b * 128 + wz)) * 4096 + n0];
        uint32_t ma1 = Mb[((size_t)(b * 128 + wz + 1)) * 4096 + n0];
        uint32_t mb0 = Mb[((size_t)(b * 128 + wz)) * 4096 + n1];
        uint32_t mb1 = Mb[((size_t)(b * 128 + wz + 1)) * 4096 + n1];
        __syncthreads();

        float c[8][4];
#pragma unroll
        for (int j = 0; j < 8; ++j) {
            c[j][0] = c[j][1] = c[j][2] = c[j][3] = 0.f;
#pragma unroll
            for (int kc = 0; kc < 4; ++kc) {
                uint32_t b0 = Ks[(j * 8 + qr) * 36 + kc * 8 + qc];
                uint32_t b1 = Ks[(j * 8 + qr) * 36 + kc * 8 + qc + 4];
                mma_f16(c[j], qa[kc], b0, b1);
            }
        }
        float rx0 = -1e30f, rx1 = -1e30f;
#pragma unroll
        for (int j = 0; j < 8; ++j) {
            int bi = j * 8 + qc * 2;
            uint32_t w0 = (bi < 32) ? ma0 : ma1;
            uint32_t w1 = (bi < 32) ? mb0 : mb1;
            int sh = bi & 31;
            if ((w0 >> sh) & 1u)       c[j][0] = -1e30f;
            if ((w0 >> (sh + 1)) & 1u) c[j][1] = -1e30f;
            if ((w1 >> sh) & 1u)       c[j][2] = -1e30f;
            if ((w1 >> (sh + 1)) & 1u) c[j][3] = -1e30f;
            rx0 = fmaxf(rx0, fmaxf(c[j][0], c[j][1]));
            rx1 = fmaxf(rx1, fmaxf(c[j][2], c[j][3]));
        }
        rx0 = fmaxf(rx0, __shfl_xor_sync(0xffffffffu, rx0, 1));
        rx0 = fmaxf(rx0, __shfl_xor_sync(0xffffffffu, rx0, 2));
        rx1 = fmaxf(rx1, __shfl_xor_sync(0xffffffffu, rx1, 1));
        rx1 = fmaxf(rx1, __shfl_xor_sync(0xffffffffu, rx1, 2));
        float mn0 = fmaxf(m0r, rx0), mn1 = fmaxf(m1r, rx1);
        float cr0 = ex2f(m0r - mn0), cr1 = ex2f(m1r - mn1);
        m0r = mn0; m1r = mn1;
        l0 *= cr0; l1 *= cr1;
#pragma unroll
        for (int j = 0; j < 8; ++j) {
            o[j][0] *= cr0; o[j][1] *= cr0; o[j][2] *= cr1; o[j][3] *= cr1;
        }
#pragma unroll
        for (int j = 0; j < 8; ++j) {
            c[j][0] = ex2f(c[j][0] - m0r); c[j][1] = ex2f(c[j][1] - m0r);
            c[j][2] = ex2f(c[j][2] - m1r); c[j][3] = ex2f(c[j][3] - m1r);
            l0 += c[j][0] + c[j][1];
            l1 += c[j][2] + c[j][3];
        }
#pragma unroll
        for (int kc = 0; kc < 4; ++kc) {
            uint32_t pa[4];
            pa[0] = pack_h2(c[2 * kc][0], c[2 * kc][1]);
            pa[1] = pack_h2(c[2 * kc][2], c[2 * kc][3]);
            pa[2] = pack_h2(c[2 * kc + 1][0], c[2 * kc + 1][1]);
            pa[3] = pack_h2(c[2 * kc + 1][2], c[2 * kc + 1][3]);
#pragma unroll
            for (int nd = 0; nd < 8; ++nd) {
                uint32_t b0 = Vs[(nd * 8 + qr) * 36 + kc * 8 + qc];
                uint32_t b1 = Vs[(nd * 8 + qr) * 36 + kc * 8 + qc + 4];
                mma_f16(o[nd], pa, b0, b1);
            }
        }
        __syncthreads();
    }

    l0 += __shfl_xor_sync(0xffffffffu, l0, 1);
    l0 += __shfl_xor_sync(0xffffffffu, l0, 2);
    l1 += __shfl_xor_sync(0xffffffffu, l1, 1);
    l1 += __shfl_xor_sync(0xffffffffu, l1, 2);
    float i0 = 1.f / fmaxf(l0, 1e-30f);
    float i1 = 1.f / fmaxf(l1, 1e-30f);
#pragma unroll
    for (int j = 0; j < 8; ++j) {
        int d = j * 8 + qc * 2;
        float2 v0 = make_float2(o[j][0] * i0, o[j][1] * i0);
        float2 v1 = make_float2(o[j][2] * i1, o[j][3] * i1);
        *(float2*)&O[((size_t)(b * 4096 + n0)) * 512 + h * 64 + d] = v0;
        *(float2*)&O[((size_t)(b * 4096 + n1)) * 512 + h * 64 + d] = v1;
    }
}

// ---------------------------------------------------------------------------
// Launch
// ---------------------------------------------------------------------------
extern "C" void kernel_launch(void* const* d_in, const int* in_sizes, int n_in,
                              void* d_out, int out_size)
{
    const float* x       = (const float*)d_in[0];
    const float* context = (const float*)d_in[1];
    const int*   pos_x   = (const int*)d_in[2];
    const int*   pos_ctx = (const int*)d_in[3];
    const unsigned char* mask = (const unsigned char*)d_in[4];
    const float* Wq = (const float*)d_in[5];
    const float* bq = (const float*)d_in[6];
    const float* Wk = (const float*)d_in[7];
    const float* bk = (const float*)d_in[8];
    const float* Wv = (const float*)d_in[9];
    const float* bv = (const float*)d_in[10];
    const float* Wo = (const float*)d_in[11];
    const float* bo = (const float*)d_in[12];
    float* out = (float*)d_out;

    float *qp, *kp, *vp, *op;
    __half *qh, *kh;
    uint32_t *vt, *mb;
    __half *xh, *xl, *chh, *cl, *wth, *wtl;
    cudaGetSymbolAddress((void**)&qp, g_Q);
    cudaGetSymbolAddress((void**)&kp, g_K);
    cudaGetSymbolAddress((void**)&vp, g_V);
    cudaGetSymbolAddress((void**)&op, g_O);
    cudaGetSymbolAddress((void**)&qh, g_Qh);
    cudaGetSymbolAddress((void**)&kh, g_Kh);
    cudaGetSymbolAddress((void**)&vt, g_Vt);
    cudaGetSymbolAddress((void**)&mb, g_Mbits);
    cudaGetSymbolAddress((void**)&xh, g_Xh);
    cudaGetSymbolAddress((void**)&xl, g_Xl);
    cudaGetSymbolAddress((void**)&chh, g_Ch);
    cudaGetSymbolAddress((void**)&cl, g_Cl);
    cudaGetSymbolAddress((void**)&wth, g_Wth);
    cudaGetSymbolAddress((void**)&wtl, g_Wtl);

    detect_mask_kernel<<<1, 256>>>((const uint32_t*)mask);
    pack_mask_kernel<<<BATCH * SEQ_N, 128>>>(mask, mb);

    // weight transpose + split (4 weights into one packed buffer)
    const int WSZ = DIM_C * DIM_C;               // elements
    dim3 wgrid(8, 8);
    wsplit_kernel<<<wgrid, 256>>>(Wq, (uint32_t*)(wth) + 0 * WSZ / 2, (uint32_t*)(wtl) + 0 * WSZ / 2);
    wsplit_kernel<<<wgrid, 256>>>(Wk, (uint32_t*)(wth) + 1 * WSZ / 2, (uint32_t*)(wtl) + 1 * WSZ / 2);
    wsplit_kernel<<<wgrid, 256>>>(Wv, (uint32_t*)(wth) + 2 * WSZ / 2, (uint32_t*)(wtl) + 2 * WSZ / 2);
    wsplit_kernel<<<wgrid, 256>>>(Wo, (uint32_t*)(wth) + 3 * WSZ / 2, (uint32_t*)(wtl) + 3 * WSZ / 2);

    // input splits
    const int n4 = BATCH * SEQ_N * DIM_C / 4;    // 1,048,576
    split_kernel<<<n4 / 256, 256>>>((const float4*)x, (uint2*)xh, (uint2*)xl, n4);
    split_kernel<<<n4 / 256, 256>>>((const float4*)context, (uint2*)chh, (uint2*)cl, n4);

    dim3 ggrid(DIM_C / 64, (BATCH * SEQ_N) / 128);   // (8, 64)
    gemm_mma_kernel<<<ggrid, 256>>>((const uint32_t*)xh, (const uint32_t*)xl,
                                    (const uint32_t*)wth + 0 * WSZ / 2,
                                    (const uint32_t*)wtl + 0 * WSZ / 2, bq, qp);
    gemm_mma_kernel<<<ggrid, 256>>>((const uint32_t*)chh, (const uint32_t*)cl,
                                    (const uint32_t*)wth + 1 * WSZ / 2,
                                    (const uint32_t*)wtl + 1 * WSZ / 2, bk, kp);
    gemm_mma_kernel<<<ggrid, 256>>>((const uint32_t*)chh, (const uint32_t*)cl,
                                    (const uint32_t*)wth + 2 * WSZ / 2,
                                    (const uint32_t*)wtl + 2 * WSZ / 2, bv, vp);

    const int rope_total = BATCH * SEQ_N * HEADS * 32;
    const float qscale = 0.125f * 1.4426950408889634f;
    rope2d_h_kernel<<<(rope_total + 255) / 256, 256>>>(qp, qh, pos_x, qscale, rope_total);
    rope2d_h_kernel<<<(rope_total + 255) / 256, 256>>>(kp, kh, pos_ctx, 1.0f, rope_total);

    dim3 vgrid(SEQ_M / 64, HEADS, BATCH);
    vtrans_kernel<<<vgrid, 256>>>(vp, vt);

    dim3 agrid(SEQ_N / 128, HEADS, BATCH);
    attn_mma_kernel<<<agrid, 256>>>((const uint32_t*)qh, (const uint32_t*)kh,
                                    vt, mb, op);

    // O projection: split attention output (reuse x split buffers)
    split_kernel<<<n4 / 256, 256>>>((const float4*)op, (uint2*)xh, (uint2*)xl, n4);
    gemm_mma_kernel<<<ggrid, 256>>>((const uint32_t*)xh, (const uint32_t*)xl,
                                    (const uint32_t*)wth + 3 * WSZ / 2,
                                    (const uint32_t*)wtl + 3 * WSZ / 2, bo, out);
}

// round 5
// speedup vs baseline: 6.2665x; 1.0850x over previous
#include <cuda_runtime.h>
#include <cuda_fp16.h>
#include <cstdint>

#define BATCH 2
#define SEQ_N 4096
#define SEQ_M 4096
#define DIM_C 512
#define HEADS 8
#define HDIM  64

// ---------------------------------------------------------------------------
// Scratch
// ---------------------------------------------------------------------------
__device__ float g_Q[BATCH * SEQ_N * DIM_C];
__device__ float g_K[BATCH * SEQ_M * DIM_C];
__device__ float g_V[BATCH * SEQ_M * DIM_C];
__device__ __half g_Qh[BATCH * HEADS * SEQ_N * HDIM];
__device__ __half g_Kh[BATCH * HEADS * SEQ_M * HDIM];
__device__ __half g_Vt[BATCH * HEADS * HDIM * SEQ_M];
__device__ uint32_t g_Mbits[BATCH * 128 * SEQ_N];
__device__ int g_maskBool;
__device__ __half g_Xh[BATCH * SEQ_N * DIM_C];
__device__ __half g_Xl[BATCH * SEQ_N * DIM_C];
__device__ __half g_Ch[BATCH * SEQ_M * DIM_C];
__device__ __half g_Cl[BATCH * SEQ_M * DIM_C];
__device__ __half g_Wth[4 * DIM_C * DIM_C];   // transposed [n][k]
__device__ __half g_Wtl[4 * DIM_C * DIM_C];

// ---------------------------------------------------------------------------
// helpers
// ---------------------------------------------------------------------------
__device__ __forceinline__ float ex2f(float x) {
    float y; asm("ex2.approx.ftz.f32 %0, %1;" : "=f"(y) : "f"(x)); return y;
}
__device__ __forceinline__ uint32_t pack_h2(float lo, float hi) {
    uint32_t r; asm("cvt.rn.f16x2.f32 %0, %1, %2;" : "=r"(r) : "f"(hi), "f"(lo)); return r;
}
__device__ __forceinline__ void mma_f16(float c[4], const uint32_t a[4],
                                        uint32_t b0, uint32_t b1) {
    asm volatile(
        "mma.sync.aligned.m16n8k16.row.col.f32.f16.f16.f32 "
        "{%0,%1,%2,%3}, {%4,%5,%6,%7}, {%8,%9}, {%0,%1,%2,%3};"
        : "+f"(c[0]), "+f"(c[1]), "+f"(c[2]), "+f"(c[3])
        : "r"(a[0]), "r"(a[1]), "r"(a[2]), "r"(a[3]), "r"(b0), "r"(b1));
}
__device__ __forceinline__ void ldsm_x4(uint32_t r[4], uint32_t addr) {
    asm volatile("ldmatrix.sync.aligned.m8n8.x4.shared.b16 {%0,%1,%2,%3}, [%4];"
                 : "=r"(r[0]), "=r"(r[1]), "=r"(r[2]), "=r"(r[3]) : "r"(addr));
}
__device__ __forceinline__ uint32_t smem_u32(const void* p) {
    return (uint32_t)__cvta_generic_to_shared(p);
}

// ---------------------------------------------------------------------------
// Mask dtype detection + packing (verified)
// ---------------------------------------------------------------------------
__global__ void detect_mask_kernel(const uint32_t* __restrict__ m)
{
    __shared__ int found;
    if (threadIdx.x == 0) found = 0;
    __syncthreads();
    uint32_t v = m[threadIdx.x] | m[threadIdx.x + 256] |
                 m[threadIdx.x + 512] | m[threadIdx.x + 768];
    if (v > 1u) atomicOr(&found, 1);
    __syncthreads();
    if (threadIdx.x == 0) g_maskBool = found;
}

__global__ __launch_bounds__(128) void pack_mask_kernel(
    const unsigned char* __restrict__ mraw, uint32_t* __restrict__ out)
{
    const int bn = blockIdx.x;
    const int w  = threadIdx.x;
    const int b  = bn >> 12;
    const int n  = bn & 4095;
    uint32_t bits = 0;
    if (g_maskBool) {
        const uint32_t* p = (const uint32_t*)(mraw + (size_t)bn * 4096) + w * 8;
#pragma unroll
        for (int i = 0; i < 8; ++i) {
            uint32_t v = p[i];
#pragma unroll
            for (int j = 0; j < 4; ++j)
                if ((v >> (j * 8)) & 0xFFu) bits |= 1u << (i * 4 + j);
        }
    } else {
        const int* p = (const int*)mraw + (size_t)bn * 4096 + w * 32;
#pragma unroll
        for (int i = 0; i < 32; ++i)
            if (p[i] != 0) bits |= 1u << i;
    }
    out[((size_t)(b * 128 + w)) * 4096 + n] = bits;
}

// ---------------------------------------------------------------------------
// All 4 weights: transpose + fp16 split in one launch (grid z = weight id)
// ---------------------------------------------------------------------------
__global__ __launch_bounds__(256) void wsplit4_kernel(
    const float* __restrict__ W0, const float* __restrict__ W1,
    const float* __restrict__ W2, const float* __restrict__ W3,
    uint32_t* __restrict__ Wth, uint32_t* __restrict__ Wtl)
{
    const int z = blockIdx.z;
    const float* W = (z == 0) ? W0 : (z == 1) ? W1 : (z == 2) ? W2 : W3;
    uint32_t* oh = Wth + (size_t)z * (DIM_C * DIM_C / 2);
    uint32_t* ol = Wtl + (size_t)z * (DIM_C * DIM_C / 2);

    const int n0 = blockIdx.x * 64;
    const int k0 = blockIdx.y * 64;
    const int t  = threadIdx.x;
    __shared__ float S[64][65];
#pragma unroll
    for (int i = 0; i < 16; ++i) {
        int e = i * 256 + t;
        int r = e >> 6, c = e & 63;
        S[r][c] = W[(size_t)(k0 + r) * 512 + n0 + c];
    }
    __syncthreads();
#pragma unroll
    for (int i = 0; i < 8; ++i) {
        int e = i * 256 + t;
        int n = e >> 5, kw = e & 31;
        float v0 = S[2 * kw][n], v1 = S[2 * kw + 1][n];
        __half h0 = __float2half(v0), h1 = __float2half(v1);
        float r0 = v0 - __half2float(h0), r1 = v1 - __half2float(h1);
        size_t dst = (size_t)(n0 + n) * 256 + (k0 >> 1) + kw;
        oh[dst] = ((uint32_t)__half_as_ushort(h1) << 16) | __half_as_ushort(h0);
        ol[dst] = pack_h2(r0, r1);
    }
}

// ---------------------------------------------------------------------------
// x and context fp16 splits in one launch (grid y = which input)
// ---------------------------------------------------------------------------
__global__ void split2_kernel(const float4* __restrict__ x, const float4* __restrict__ ctx,
                              uint2* __restrict__ xh, uint2* __restrict__ xl,
                              uint2* __restrict__ ch, uint2* __restrict__ cl, int n4)
{
    int i = blockIdx.x * blockDim.x + threadIdx.x;
    if (i >= n4) return;
    const float4* s = blockIdx.y ? ctx : x;
    uint2* oh = blockIdx.y ? ch : xh;
    uint2* ol = blockIdx.y ? cl : xl;
    float4 v = s[i];
    __half hx = __float2half(v.x), hy = __float2half(v.y);
    __half hz = __float2half(v.z), hw = __float2half(v.w);
    uint2 h, l;
    h.x = ((uint32_t)__half_as_ushort(hy) << 16) | __half_as_ushort(hx);
    h.y = ((uint32_t)__half_as_ushort(hw) << 16) | __half_as_ushort(hz);
    l.x = pack_h2(v.x - __half2float(hx), v.y - __half2float(hy));
    l.y = pack_h2(v.z - __half2float(hz), v.w - __half2float(hw));
    oh[i] = h;
    ol[i] = l;
}

// ---------------------------------------------------------------------------
// Tensor-core GEMM, fp16 split (3-product), ldmatrix fragments.
// Block tile 128x128, BK=32, 256 thr = 8 warps, warp tile 32x64.
// ---------------------------------------------------------------------------
__global__ __launch_bounds__(256, 2) void gemm_mma_kernel(
    const uint32_t* __restrict__ Ah, const uint32_t* __restrict__ Al,
    const uint32_t* __restrict__ Wth, const uint32_t* __restrict__ Wtl,
    const float* __restrict__ bias, float* __restrict__ Y)
{
    const int row0 = blockIdx.y * 128;
    const int col0 = blockIdx.x * 128;
    const int t = threadIdx.x, w = t >> 5, lane = t & 31;
    const int wm = w & 3, wn = w >> 2;
    const int qr = lane >> 2, qc = lane & 3;

    __shared__ uint32_t Ahs[128 * 20];
    __shared__ uint32_t Als[128 * 20];
    __shared__ uint32_t Whs[128 * 20];
    __shared__ uint32_t Wls[128 * 20];

    float acc[2][8][4];
#pragma unroll
    for (int mt = 0; mt < 2; ++mt)
#pragma unroll
        for (int n = 0; n < 8; ++n)
#pragma unroll
            for (int k = 0; k < 4; ++k) acc[mt][n][k] = 0.f;

    // ldmatrix lane address components
    const int a_row = wm * 32 + (lane & 7) + ((lane >> 3) & 1) * 8;
    const int a_wrd = (lane >> 4) * 4;
    const uint32_t ah_b = smem_u32(Ahs) + (a_row * 20 + a_wrd) * 4;
    const uint32_t al_b = smem_u32(Als) + (a_row * 20 + a_wrd) * 4;
    const int b_row = wn * 64 + (lane & 7);
    const int b_wrd = (lane >> 3) * 4;
    const uint32_t wh_b = smem_u32(Whs) + (b_row * 20 + b_wrd) * 4;
    const uint32_t wl_b = smem_u32(Wls) + (b_row * 20 + b_wrd) * 4;

    const int ldr = t >> 1;            // 0..127
    const int ldc = (t & 1) * 8;       // 0 or 8

    for (int ch = 0; ch < 16; ++ch) {
        const int kw = ch * 16;
        const size_t ga = (size_t)(row0 + ldr) * 256 + kw + ldc;
        const size_t gw = (size_t)(col0 + ldr) * 256 + kw + ldc;
        uint4 va0 = *(const uint4*)&Ah[ga];
        uint4 va1 = *(const uint4*)&Ah[ga + 4];
        uint4 vb0 = *(const uint4*)&Al[ga];
        uint4 vb1 = *(const uint4*)&Al[ga + 4];
        uint4 vw0 = *(const uint4*)&Wth[gw];
        uint4 vw1 = *(const uint4*)&Wth[gw + 4];
        uint4 vl0 = *(const uint4*)&Wtl[gw];
        uint4 vl1 = *(const uint4*)&Wtl[gw + 4];
        *(uint4*)&Ahs[ldr * 20 + ldc]     = va0;
        *(uint4*)&Ahs[ldr * 20 + ldc + 4] = va1;
        *(uint4*)&Als[ldr * 20 + ldc]     = vb0;
        *(uint4*)&Als[ldr * 20 + ldc + 4] = vb1;
        *(uint4*)&Whs[ldr * 20 + ldc]     = vw0;
        *(uint4*)&Whs[ldr * 20 + ldc + 4] = vw1;
        *(uint4*)&Wls[ldr * 20 + ldc]     = vl0;
        *(uint4*)&Wls[ldr * 20 + ldc + 4] = vl1;
        __syncthreads();

        uint32_t ahi[2][2][4], alo[2][2][4];
#pragma unroll
        for (int mt = 0; mt < 2; ++mt)
#pragma unroll
            for (int kc = 0; kc < 2; ++kc) {
                ldsm_x4(ahi[mt][kc], ah_b + (mt * 16 * 20 + kc * 8) * 4);
                ldsm_x4(alo[mt][kc], al_b + (mt * 16 * 20 + kc * 8) * 4);
            }
#pragma unroll
        for (int n = 0; n < 8; ++n) {
            uint32_t bh[4], bl[4];
            ldsm_x4(bh, wh_b + n * 8 * 20 * 4);   // {b0kc0,b1kc0,b0kc1,b1kc1}
            ldsm_x4(bl, wl_b + n * 8 * 20 * 4);
#pragma unroll
            for (int mt = 0; mt < 2; ++mt) {
                mma_f16(acc[mt][n], ahi[mt][0], bh[0], bh[1]);
                mma_f16(acc[mt][n], ahi[mt][1], bh[2], bh[3]);
                mma_f16(acc[mt][n], alo[mt][0], bh[0], bh[1]);
                mma_f16(acc[mt][n], alo[mt][1], bh[2], bh[3]);
                mma_f16(acc[mt][n], ahi[mt][0], bl[0], bl[1]);
                mma_f16(acc[mt][n], ahi[mt][1], bl[2], bl[3]);
            }
        }
        __syncthreads();
    }

#pragma unroll
    for (int mt = 0; mt < 2; ++mt)
#pragma unroll
        for (int n = 0; n < 8; ++n) {
            int row = row0 + wm * 32 + mt * 16 + qr;
            int col = col0 + wn * 64 + n * 8 + qc * 2;
            float2 bi = *(const float2*)&bias[col];
            float2 v0 = make_float2(acc[mt][n][0] + bi.x, acc[mt][n][1] + bi.y);
            float2 v1 = make_float2(acc[mt][n][2] + bi.x, acc[mt][n][3] + bi.y);
            *(float2*)&Y[(size_t)row * 512 + col] = v0;
            *(float2*)&Y[(size_t)(row + 8) * 512 + col] = v1;
        }
}

// ---------------------------------------------------------------------------
// RoPE 2D: fp32 [b,n,h,64] -> fp16 [b,h,n,64], scale folded in.
// ---------------------------------------------------------------------------
__global__ void rope2d_h_kernel(const float* __restrict__ src, __half* __restrict__ dst,
                                const int* __restrict__ pos, float qscale, int total)
{
    int idx = blockIdx.x * blockDim.x + threadIdx.x;
    if (idx >= total) return;
    int pair = idx & 31;
    int h    = (idx >> 5) & 7;
    int n    = (idx >> 8) & 4095;
    int b    = idx >> 20;
    int blk  = pair >> 4;
    int ii   = pair & 15;

    float invf = exp2f(-(float)ii * 0.41524101186092864f);
    int p = pos[((size_t)(b * 4096 + n)) * 2 + blk];
    float ang = (float)p * invf;
    float sn, cs;
    sincosf(ang, &sn, &cs);

    size_t sbase = ((size_t)(b * 4096 + n) * 8 + h) * 64 + blk * 32 + ii;
    float v1 = src[sbase];
    float v2 = src[sbase + 16];
    size_t dbase = ((size_t)((b * 8 + h) * 4096 + n)) * 64 + blk * 32 + ii;
    dst[dbase]      = __float2half((v1 * cs - v2 * sn) * qscale);
    dst[dbase + 16] = __float2half((v2 * cs + v1 * sn) * qscale);
}

// ---------------------------------------------------------------------------
// V: fp32 [b,m,(h,d)] -> fp16 transposed [b,h,d,m]
// ---------------------------------------------------------------------------
__global__ __launch_bounds__(256) void vtrans_kernel(
    const float* __restrict__ V, uint32_t* __restrict__ Vt)
{
    const int m0 = blockIdx.x * 64;
    const int h  = blockIdx.y;
    const int b  = blockIdx.z;
    const int t  = threadIdx.x;
    __shared__ float S[64][65];
#pragma unroll
    for (int i = 0; i < 16; ++i) {
        int e = i * 256 + t;
        int m = e >> 6, d = e & 63;
        S[m][d] = V[((size_t)(b * 4096 + m0 + m)) * 512 + h * 64 + d];
    }
    __syncthreads();
#pragma unroll
    for (int i = 0; i < 8; ++i) {
        int e = i * 256 + t;
        int d = e >> 5, mm = e & 31;
        uint32_t v = pack_h2(S[2 * mm][d], S[2 * mm + 1][d]);
        Vt[((size_t)((b * 8 + h) * 64 + d)) * 2048 + (m0 >> 1) + mm] = v;
    }
}

// ---------------------------------------------------------------------------
// Flash attention, ldmatrix fragments, fused hi/lo fp16 output split.
// ---------------------------------------------------------------------------
__global__ __launch_bounds__(256) void attn_mma_kernel(
    const uint32_t* __restrict__ Qh, const uint32_t* __restrict__ Kh,
    const uint32_t* __restrict__ Vt, const uint32_t* __restrict__ Mb,
    uint32_t* __restrict__ Oh, uint32_t* __restrict__ Ol)
{
    const int b = blockIdx.z, h = blockIdx.y;
    const int q0 = blockIdx.x * 128;
    const int t = threadIdx.x, w = t >> 5, lane = t & 31;
    const int qr = lane >> 2, qc = lane & 3;

    __shared__ uint32_t Ks[64 * 36];
    __shared__ uint32_t Vs[64 * 36];

    const size_t bh = (size_t)(b * 8 + h);
    const int n0 = q0 + w * 16 + qr;
    const int n1 = n0 + 8;

    // ldmatrix lane base for B-operand tiles (rows = 8 keys / 8 dims)
    const uint32_t lm_off = (((lane & 7) * 36 + (lane >> 3) * 4)) * 4;
    const uint32_t ks_b = smem_u32(Ks) + lm_off;
    const uint32_t vs_b = smem_u32(Vs) + lm_off;

    uint32_t qa[4][4];
    {
        const uint32_t* Qb = Qh + (bh * 4096 + q0 + (size_t)w * 16) * 32;
#pragma unroll
        for (int kc = 0; kc < 4; ++kc) {
            qa[kc][0] = Qb[qr * 32 + kc * 8 + qc];
            qa[kc][1] = Qb[(qr + 8) * 32 + kc * 8 + qc];
            qa[kc][2] = Qb[qr * 32 + kc * 8 + qc + 4];
            qa[kc][3] = Qb[(qr + 8) * 32 + kc * 8 + qc + 4];
        }
    }

    float o[8][4];
#pragma unroll
    for (int j = 0; j < 8; ++j)
#pragma unroll
        for (int k = 0; k < 4; ++k) o[j][k] = 0.f;
    float m0r = -1e30f, m1r = -1e30f, l0 = 0.f, l1 = 0.f;

    const uint32_t* Kg = Kh + bh * SEQ_M * 32;
    const uint32_t* Vg = Vt + bh * HDIM * 2048;

    for (int mt = 0; mt < SEQ_M / 64; ++mt) {
        const int mk = mt * 64;
#pragma unroll
        for (int i = 0; i < 8; ++i) {
            int e = i * 256 + t;
            int row = e >> 5, col = e & 31;
            Ks[row * 36 + col] = Kg[(size_t)(mk + row) * 32 + col];
            Vs[row * 36 + col] = Vg[(size_t)row * 2048 + (mk >> 1) + col];
        }
        const int wz = mk >> 5;
        uint32_t ma0 = Mb[((size_t)(b * 128 + wz)) * 4096 + n0];
        uint32_t ma1 = Mb[((size_t)(b * 128 + wz + 1)) * 4096 + n0];
        uint32_t mb0 = Mb[((size_t)(b * 128 + wz)) * 4096 + n1];
        uint32_t mb1 = Mb[((size_t)(b * 128 + wz + 1)) * 4096 + n1];
        __syncthreads();

        // ---- scores ----
        float c[8][4];
#pragma unroll
        for (int j = 0; j < 8; ++j) {
            c[j][0] = c[j][1] = c[j][2] = c[j][3] = 0.f;
            uint32_t k1[4], k2[4];
            uint32_t ka = ks_b + j * 8 * 36 * 4;
            ldsm_x4(k1, ka);        // kc0: {b0,b1}, kc1: {b0,b1}
            ldsm_x4(k2, ka + 64);   // kc2, kc3
            mma_f16(c[j], qa[0], k1[0], k1[1]);
            mma_f16(c[j], qa[1], k1[2], k1[3]);
            mma_f16(c[j], qa[2], k2[0], k2[1]);
            mma_f16(c[j], qa[3], k2[2], k2[3]);
        }
        // ---- mask + row max ----
        float rx0 = -1e30f, rx1 = -1e30f;
#pragma unroll
        for (int j = 0; j < 8; ++j) {
            int bi = j * 8 + qc * 2;
            uint32_t w0 = (bi < 32) ? ma0 : ma1;
            uint32_t w1 = (bi < 32) ? mb0 : mb1;
            int sh = bi & 31;
            if ((w0 >> sh) & 1u)       c[j][0] = -1e30f;
            if ((w0 >> (sh + 1)) & 1u) c[j][1] = -1e30f;
            if ((w1 >> sh) & 1u)       c[j][2] = -1e30f;
            if ((w1 >> (sh + 1)) & 1u) c[j][3] = -1e30f;
            rx0 = fmaxf(rx0, fmaxf(c[j][0], c[j][1]));
            rx1 = fmaxf(rx1, fmaxf(c[j][2], c[j][3]));
        }
        rx0 = fmaxf(rx0, __shfl_xor_sync(0xffffffffu, rx0, 1));
        rx0 = fmaxf(rx0, __shfl_xor_sync(0xffffffffu, rx0, 2));
        rx1 = fmaxf(rx1, __shfl_xor_sync(0xffffffffu, rx1, 1));
        rx1 = fmaxf(rx1, __shfl_xor_sync(0xffffffffu, rx1, 2));
        float mn0 = fmaxf(m0r, rx0), mn1 = fmaxf(m1r, rx1);
        float cr0 = ex2f(m0r - mn0), cr1 = ex2f(m1r - mn1);
        m0r = mn0; m1r = mn1;
        l0 *= cr0; l1 *= cr1;
#pragma unroll
        for (int j = 0; j < 8; ++j) {
            o[j][0] *= cr0; o[j][1] *= cr0; o[j][2] *= cr1; o[j][3] *= cr1;
        }
#pragma unroll
        for (int j = 0; j < 8; ++j) {
            c[j][0] = ex2f(c[j][0] - m0r); c[j][1] = ex2f(c[j][1] - m0r);
            c[j][2] = ex2f(c[j][2] - m1r); c[j][3] = ex2f(c[j][3] - m1r);
            l0 += c[j][0] + c[j][1];
            l1 += c[j][2] + c[j][3];
        }
        // ---- P fragments (all 4 kc), then O += P V ----
        uint32_t pa[4][4];
#pragma unroll
        for (int kc = 0; kc < 4; ++kc) {
            pa[kc][0] = pack_h2(c[2 * kc][0], c[2 * kc][1]);
            pa[kc][1] = pack_h2(c[2 * kc][2], c[2 * kc][3]);
            pa[kc][2] = pack_h2(c[2 * kc + 1][0], c[2 * kc + 1][1]);
            pa[kc][3] = pack_h2(c[2 * kc + 1][2], c[2 * kc + 1][3]);
        }
#pragma unroll
        for (int nd = 0; nd < 8; ++nd) {
            uint32_t v1[4], v2[4];
            uint32_t va = vs_b + nd * 8 * 36 * 4;
            ldsm_x4(v1, va);
            ldsm_x4(v2, va + 64);
            mma_f16(o[nd], pa[0], v1[0], v1[1]);
            mma_f16(o[nd], pa[1], v1[2], v1[3]);
            mma_f16(o[nd], pa[2], v2[0], v2[1]);
            mma_f16(o[nd], pa[3], v2[2], v2[3]);
        }
        __syncthreads();
    }

    l0 += __shfl_xor_sync(0xffffffffu, l0, 1);
    l0 += __shfl_xor_sync(0xffffffffu, l0, 2);
    l1 += __shfl_xor_sync(0xffffffffu, l1, 1);
    l1 += __shfl_xor_sync(0xffffffffu, l1, 2);
    float i0 = 1.f / fmaxf(l0, 1e-30f);
    float i1 = 1.f / fmaxf(l1, 1e-30f);
#pragma unroll
    for (int j = 0; j < 8; ++j) {
        int colw = h * 32 + j * 4 + qc;          // word index within 256-word row
        float v0 = o[j][0] * i0, v1 = o[j][1] * i0;
        float v2 = o[j][2] * i1, v3 = o[j][3] * i1;
        __half h0 = __float2half(v0), h1 = __float2half(v1);
        __half h2 = __float2half(v2), h3 = __float2half(v3);
        Oh[(size_t)n0 * 256 + (size_t)b * 4096 * 256 + colw] =
            ((uint32_t)__half_as_ushort(h1) << 16) | __half_as_ushort(h0);
        Ol[(size_t)n0 * 256 + (size_t)b * 4096 * 256 + colw] =
            pack_h2(v0 - __half2float(h0), v1 - __half2float(h1));
        Oh[(size_t)n1 * 256 + (size_t)b * 4096 * 256 + colw] =
            ((uint32_t)__half_as_ushort(h3) << 16) | __half_as_ushort(h2);
        Ol[(size_t)n1 * 256 + (size_t)b * 4096 * 256 + colw] =
            pack_h2(v2 - __half2float(h2), v3 - __half2float(h3));
    }
}

// ---------------------------------------------------------------------------
// Launch
// ---------------------------------------------------------------------------
extern "C" void kernel_launch(void* const* d_in, const int* in_sizes, int n_in,
                              void* d_out, int out_size)
{
    const float* x       = (const float*)d_in[0];
    const float* context = (const float*)d_in[1];
    const int*   pos_x   = (const int*)d_in[2];
    const int*   pos_ctx = (const int*)d_in[3];
    const unsigned char* mask = (const unsigned char*)d_in[4];
    const float* Wq = (const float*)d_in[5];
    const float* bq = (const float*)d_in[6];
    const float* Wk = (const float*)d_in[7];
    const float* bk = (const float*)d_in[8];
    const float* Wv = (const float*)d_in[9];
    const float* bv = (const float*)d_in[10];
    const float* Wo = (const float*)d_in[11];
    const float* bo = (const float*)d_in[12];
    float* out = (float*)d_out;

    float *qp, *kp, *vp;
    __half *qh, *kh;
    uint32_t *vt, *mb;
    __half *xh, *xl, *chh, *cl, *wth, *wtl;
    cudaGetSymbolAddress((void**)&qp, g_Q);
    cudaGetSymbolAddress((void**)&kp, g_K);
    cudaGetSymbolAddress((void**)&vp, g_V);
    cudaGetSymbolAddress((void**)&qh, g_Qh);
    cudaGetSymbolAddress((void**)&kh, g_Kh);
    cudaGetSymbolAddress((void**)&vt, g_Vt);
    cudaGetSymbolAddress((void**)&mb, g_Mbits);
    cudaGetSymbolAddress((void**)&xh, g_Xh);
    cudaGetSymbolAddress((void**)&xl, g_Xl);
    cudaGetSymbolAddress((void**)&chh, g_Ch);
    cudaGetSymbolAddress((void**)&cl, g_Cl);
    cudaGetSymbolAddress((void**)&wth, g_Wth);
    cudaGetSymbolAddress((void**)&wtl, g_Wtl);

    const int WSZ2 = DIM_C * DIM_C / 2;      // words per weight

    detect_mask_kernel<<<1, 256>>>((const uint32_t*)mask);
    pack_mask_kernel<<<BATCH * SEQ_N, 128>>>(mask, mb);

    dim3 wgrid(8, 8, 4);
    wsplit4_kernel<<<wgrid, 256>>>(Wq, Wk, Wv, Wo, (uint32_t*)wth, (uint32_t*)wtl);

    const int n4 = BATCH * SEQ_N * DIM_C / 4;
    dim3 sgrid(n4 / 256, 2);
    split2_kernel<<<sgrid, 256>>>((const float4*)x, (const float4*)context,
                                  (uint2*)xh, (uint2*)xl, (uint2*)chh, (uint2*)cl, n4);

    dim3 ggrid(DIM_C / 128, (BATCH * SEQ_N) / 128);   // (4, 64)
    gemm_mma_kernel<<<ggrid, 256>>>((const uint32_t*)xh, (const uint32_t*)xl,
                                    (const uint32_t*)wth + 0 * WSZ2,
                                    (const uint32_t*)wtl + 0 * WSZ2, bq, qp);
    gemm_mma_kernel<<<ggrid, 256>>>((const uint32_t*)chh, (const uint32_t*)cl,
                                    (const uint32_t*)wth + 1 * WSZ2,
                                    (const uint32_t*)wtl + 1 * WSZ2, bk, kp);
    gemm_mma_kernel<<<ggrid, 256>>>((const uint32_t*)chh, (const uint32_t*)cl,
                                    (const uint32_t*)wth + 2 * WSZ2,
                                    (const uint32_t*)wtl + 2 * WSZ2, bv, vp);

    const int rope_total = BATCH * SEQ_N * HEADS * 32;
    const float qscale = 0.125f * 1.4426950408889634f;
    rope2d_h_kernel<<<(rope_total + 255) / 256, 256>>>(qp, qh, pos_x, qscale, rope_total);
    rope2d_h_kernel<<<(rope_total + 255) / 256, 256>>>(kp, kh, pos_ctx, 1.0f, rope_total);

    dim3 vgrid(SEQ_M / 64, HEADS, BATCH);
    vtrans_kernel<<<vgrid, 256>>>(vp, vt);

    dim3 agrid(SEQ_N / 128, HEADS, BATCH);
    attn_mma_kernel<<<agrid, 256>>>((const uint32_t*)qh, (const uint32_t*)kh,
                                    vt, mb, (uint32_t*)xh, (uint32_t*)xl);

    gemm_mma_kernel<<<ggrid, 256>>>((const uint32_t*)xh, (const uint32_t*)xl,
                                    (const uint32_t*)wth + 3 * WSZ2,
                                    (const uint32_t*)wtl + 3 * WSZ2, bo, out);
}

// round 6
// speedup vs baseline: 7.1200x; 1.1362x over previous
#include <cuda_runtime.h>
#include <cuda_fp16.h>
#include <cstdint>

#define BATCH 2
#define SEQ_N 4096
#define SEQ_M 4096
#define DIM_C 512
#define HEADS 8
#define HDIM  64

// ---------------------------------------------------------------------------
// Scratch
// ---------------------------------------------------------------------------
__device__ float g_Q[BATCH * SEQ_N * DIM_C];
__device__ float g_K[BATCH * SEQ_M * DIM_C];
__device__ float g_V[BATCH * SEQ_M * DIM_C];
__device__ __half g_Qh[BATCH * HEADS * SEQ_N * HDIM];
__device__ __half g_Kh[BATCH * HEADS * SEQ_M * HDIM];
__device__ __half g_Vt[BATCH * HEADS * HDIM * SEQ_M];
__device__ uint32_t g_Mbits[BATCH * 128 * SEQ_N];
__device__ int g_maskBool;
__device__ __half g_Xh[BATCH * SEQ_N * DIM_C];
__device__ __half g_Xl[BATCH * SEQ_N * DIM_C];
__device__ __half g_Ch[BATCH * SEQ_M * DIM_C];
__device__ __half g_Cl[BATCH * SEQ_M * DIM_C];
__device__ __half g_Wth[4 * DIM_C * DIM_C];   // transposed [n][k]
__device__ __half g_Wtl[4 * DIM_C * DIM_C];

// ---------------------------------------------------------------------------
// helpers
// ---------------------------------------------------------------------------
__device__ __forceinline__ float ex2f(float x) {
    float y; asm("ex2.approx.ftz.f32 %0, %1;" : "=f"(y) : "f"(x)); return y;
}
__device__ __forceinline__ uint32_t pack_h2(float lo, float hi) {
    uint32_t r; asm("cvt.rn.f16x2.f32 %0, %1, %2;" : "=r"(r) : "f"(hi), "f"(lo)); return r;
}
__device__ __forceinline__ void mma_f16(float c[4], const uint32_t a[4],
                                        uint32_t b0, uint32_t b1) {
    asm volatile(
        "mma.sync.aligned.m16n8k16.row.col.f32.f16.f16.f32 "
        "{%0,%1,%2,%3}, {%4,%5,%6,%7}, {%8,%9}, {%0,%1,%2,%3};"
        : "+f"(c[0]), "+f"(c[1]), "+f"(c[2]), "+f"(c[3])
        : "r"(a[0]), "r"(a[1]), "r"(a[2]), "r"(a[3]), "r"(b0), "r"(b1));
}
__device__ __forceinline__ void ldsm_x4(uint32_t r[4], uint32_t addr) {
    asm volatile("ldmatrix.sync.aligned.m8n8.x4.shared.b16 {%0,%1,%2,%3}, [%4];"
                 : "=r"(r[0]), "=r"(r[1]), "=r"(r[2]), "=r"(r[3]) : "r"(addr));
}
__device__ __forceinline__ uint32_t smem_u32(const void* p) {
    return (uint32_t)__cvta_generic_to_shared(p);
}
__device__ __forceinline__ void cp16(uint32_t smem_dst, const void* gsrc) {
    asm volatile("cp.async.cg.shared.global [%0], [%1], 16;" ::
                 "r"(smem_dst), "l"(gsrc));
}
__device__ __forceinline__ void cp_commit() {
    asm volatile("cp.async.commit_group;");
}
__device__ __forceinline__ void cp_wait1() {
    asm volatile("cp.async.wait_group 1;");
}
__device__ __forceinline__ void cp_wait0() {
    asm volatile("cp.async.wait_group 0;");
}

// ---------------------------------------------------------------------------
// Mask dtype detection + packing (verified)
// ---------------------------------------------------------------------------
__global__ void detect_mask_kernel(const uint32_t* __restrict__ m)
{
    __shared__ int found;
    if (threadIdx.x == 0) found = 0;
    __syncthreads();
    uint32_t v = m[threadIdx.x] | m[threadIdx.x + 256] |
                 m[threadIdx.x + 512] | m[threadIdx.x + 768];
    if (v > 1u) atomicOr(&found, 1);
    __syncthreads();
    if (threadIdx.x == 0) g_maskBool = found;
}

__global__ __launch_bounds__(128) void pack_mask_kernel(
    const unsigned char* __restrict__ mraw, uint32_t* __restrict__ out)
{
    const int bn = blockIdx.x;
    const int w  = threadIdx.x;
    const int b  = bn >> 12;
    const int n  = bn & 4095;
    uint32_t bits = 0;
    if (g_maskBool) {
        const uint32_t* p = (const uint32_t*)(mraw + (size_t)bn * 4096) + w * 8;
#pragma unroll
        for (int i = 0; i < 8; ++i) {
            uint32_t v = p[i];
#pragma unroll
            for (int j = 0; j < 4; ++j)
                if ((v >> (j * 8)) & 0xFFu) bits |= 1u << (i * 4 + j);
        }
    } else {
        const int* p = (const int*)mraw + (size_t)bn * 4096 + w * 32;
#pragma unroll
        for (int i = 0; i < 32; ++i)
            if (p[i] != 0) bits |= 1u << i;
    }
    out[((size_t)(b * 128 + w)) * 4096 + n] = bits;
}

// ---------------------------------------------------------------------------
// All 4 weights: transpose + fp16 split in one launch (grid z = weight id)
// ---------------------------------------------------------------------------
__global__ __launch_bounds__(256) void wsplit4_kernel(
    const float* __restrict__ W0, const float* __restrict__ W1,
    const float* __restrict__ W2, const float* __restrict__ W3,
    uint32_t* __restrict__ Wth, uint32_t* __restrict__ Wtl)
{
    const int z = blockIdx.z;
    const float* W = (z == 0) ? W0 : (z == 1) ? W1 : (z == 2) ? W2 : W3;
    uint32_t* oh = Wth + (size_t)z * (DIM_C * DIM_C / 2);
    uint32_t* ol = Wtl + (size_t)z * (DIM_C * DIM_C / 2);

    const int n0 = blockIdx.x * 64;
    const int k0 = blockIdx.y * 64;
    const int t  = threadIdx.x;
    __shared__ float S[64][65];
#pragma unroll
    for (int i = 0; i < 16; ++i) {
        int e = i * 256 + t;
        int r = e >> 6, c = e & 63;
        S[r][c] = W[(size_t)(k0 + r) * 512 + n0 + c];
    }
    __syncthreads();
#pragma unroll
    for (int i = 0; i < 8; ++i) {
        int e = i * 256 + t;
        int n = e >> 5, kw = e & 31;
        float v0 = S[2 * kw][n], v1 = S[2 * kw + 1][n];
        __half h0 = __float2half(v0), h1 = __float2half(v1);
        float r0 = v0 - __half2float(h0), r1 = v1 - __half2float(h1);
        size_t dst = (size_t)(n0 + n) * 256 + (k0 >> 1) + kw;
        oh[dst] = ((uint32_t)__half_as_ushort(h1) << 16) | __half_as_ushort(h0);
        ol[dst] = pack_h2(r0, r1);
    }
}

// ---------------------------------------------------------------------------
// x and context fp16 splits in one launch (grid y = which input)
// ---------------------------------------------------------------------------
__global__ void split2_kernel(const float4* __restrict__ x, const float4* __restrict__ ctx,
                              uint2* __restrict__ xh, uint2* __restrict__ xl,
                              uint2* __restrict__ ch, uint2* __restrict__ cl, int n4)
{
    int i = blockIdx.x * blockDim.x + threadIdx.x;
    if (i >= n4) return;
    const float4* s = blockIdx.y ? ctx : x;
    uint2* oh = blockIdx.y ? ch : xh;
    uint2* ol = blockIdx.y ? cl : xl;
    float4 v = s[i];
    __half hx = __float2half(v.x), hy = __float2half(v.y);
    __half hz = __float2half(v.z), hw = __float2half(v.w);
    uint2 h, l;
    h.x = ((uint32_t)__half_as_ushort(hy) << 16) | __half_as_ushort(hx);
    h.y = ((uint32_t)__half_as_ushort(hw) << 16) | __half_as_ushort(hz);
    l.x = pack_h2(v.x - __half2float(hx), v.y - __half2float(hy));
    l.y = pack_h2(v.z - __half2float(hz), v.w - __half2float(hw));
    oh[i] = h;
    ol[i] = l;
}

// ---------------------------------------------------------------------------
// Tensor-core GEMM, fp16 split (3-product), ldmatrix fragments,
// 2-stage cp.async pipeline. Dynamic smem: 2 stages x 40KB.
// Stage layout (words): Ah[128*20] Al[128*20] Wh[128*20] Wl[128*20]
// ---------------------------------------------------------------------------
#define GSTAGE_WORDS (4 * 128 * 20)
__global__ __launch_bounds__(256) void gemm_mma_kernel(
    const uint32_t* __restrict__ Ah, const uint32_t* __restrict__ Al,
    const uint32_t* __restrict__ Wth, const uint32_t* __restrict__ Wtl,
    const float* __restrict__ bias, float* __restrict__ Y)
{
    extern __shared__ uint32_t sm[];
    const int row0 = blockIdx.y * 128;
    const int col0 = blockIdx.x * 128;
    const int t = threadIdx.x, w = t >> 5, lane = t & 31;
    const int wm = w & 3, wn = w >> 2;
    const int qr = lane >> 2, qc = lane & 3;

    const uint32_t smb = smem_u32(sm);

    float acc[2][8][4];
#pragma unroll
    for (int mt = 0; mt < 2; ++mt)
#pragma unroll
        for (int n = 0; n < 8; ++n)
#pragma unroll
            for (int k = 0; k < 4; ++k) acc[mt][n][k] = 0.f;

    // ldmatrix lane address components (within a stage)
    const int a_row = wm * 32 + (lane & 7) + ((lane >> 3) & 1) * 8;
    const int a_wrd = (lane >> 4) * 4;
    const uint32_t ah_o = (0 * 2560 + a_row * 20 + a_wrd) * 4;
    const uint32_t al_o = (1 * 2560 + a_row * 20 + a_wrd) * 4;
    const int b_row = wn * 64 + (lane & 7);
    const int b_wrd = (lane >> 3) * 4;
    const uint32_t wh_o = (2 * 2560 + b_row * 20 + b_wrd) * 4;
    const uint32_t wl_o = (3 * 2560 + b_row * 20 + b_wrd) * 4;

    // cp.async mapping: idx=i*256+t -> row=idx>>2 (0..127), seg=(t&3)*4
    const int ld_seg = (t & 3) * 4;

    auto issue = [&](int ch, int st) {
        const int kw = ch * 16;
        const uint32_t sb = smb + st * GSTAGE_WORDS * 4;
#pragma unroll
        for (int i = 0; i < 2; ++i) {
            int row = i * 64 + (t >> 2);
            size_t ga = (size_t)(row0 + row) * 256 + kw + ld_seg;
            size_t gw = (size_t)(col0 + row) * 256 + kw + ld_seg;
            uint32_t so = (row * 20 + ld_seg) * 4;
            cp16(sb + 0 * 2560 * 4 + so, &Ah[ga]);
            cp16(sb + 1 * 2560 * 4 + so, &Al[ga]);
            cp16(sb + 2 * 2560 * 4 + so, &Wth[gw]);
            cp16(sb + 3 * 2560 * 4 + so, &Wtl[gw]);
        }
        cp_commit();
    };

    issue(0, 0);
    issue(1, 1);

    for (int ch = 0; ch < 16; ++ch) {
        if (ch < 15) cp_wait1(); else cp_wait0();
        __syncthreads();

        const uint32_t sb = smb + (ch & 1) * GSTAGE_WORDS * 4;
        uint32_t ahi[2][2][4], alo[2][2][4];
#pragma unroll
        for (int mt = 0; mt < 2; ++mt)
#pragma unroll
            for (int kc = 0; kc < 2; ++kc) {
                ldsm_x4(ahi[mt][kc], sb + ah_o + (mt * 16 * 20 + kc * 8) * 4);
                ldsm_x4(alo[mt][kc], sb + al_o + (mt * 16 * 20 + kc * 8) * 4);
            }
#pragma unroll
        for (int n = 0; n < 8; ++n) {
            uint32_t bh[4], bl[4];
            ldsm_x4(bh, sb + wh_o + n * 8 * 20 * 4);
            ldsm_x4(bl, sb + wl_o + n * 8 * 20 * 4);
#pragma unroll
            for (int mt = 0; mt < 2; ++mt) {
                mma_f16(acc[mt][n], ahi[mt][0], bh[0], bh[1]);
                mma_f16(acc[mt][n], ahi[mt][1], bh[2], bh[3]);
                mma_f16(acc[mt][n], alo[mt][0], bh[0], bh[1]);
                mma_f16(acc[mt][n], alo[mt][1], bh[2], bh[3]);
                mma_f16(acc[mt][n], ahi[mt][0], bl[0], bl[1]);
                mma_f16(acc[mt][n], ahi[mt][1], bl[2], bl[3]);
            }
        }
        __syncthreads();
        if (ch + 2 < 16) issue(ch + 2, ch & 1);
    }

#pragma unroll
    for (int mt = 0; mt < 2; ++mt)
#pragma unroll
        for (int n = 0; n < 8; ++n) {
            int row = row0 + wm * 32 + mt * 16 + qr;
            int col = col0 + wn * 64 + n * 8 + qc * 2;
            float2 bi = *(const float2*)&bias[col];
            float2 v0 = make_float2(acc[mt][n][0] + bi.x, acc[mt][n][1] + bi.y);
            float2 v1 = make_float2(acc[mt][n][2] + bi.x, acc[mt][n][3] + bi.y);
            *(float2*)&Y[(size_t)row * 512 + col] = v0;
            *(float2*)&Y[(size_t)(row + 8) * 512 + col] = v1;
        }
}

// ---------------------------------------------------------------------------
// RoPE 2D: fp32 [b,n,h,64] -> fp16 [b,h,n,64], scale folded in.
// ---------------------------------------------------------------------------
__global__ void rope2d_h_kernel(const float* __restrict__ src, __half* __restrict__ dst,
                                const int* __restrict__ pos, float qscale, int total)
{
    int idx = blockIdx.x * blockDim.x + threadIdx.x;
    if (idx >= total) return;
    int pair = idx & 31;
    int h    = (idx >> 5) & 7;
    int n    = (idx >> 8) & 4095;
    int b    = idx >> 20;
    int blk  = pair >> 4;
    int ii   = pair & 15;

    float invf = exp2f(-(float)ii * 0.41524101186092864f);
    int p = pos[((size_t)(b * 4096 + n)) * 2 + blk];
    float ang = (float)p * invf;
    float sn, cs;
    sincosf(ang, &sn, &cs);

    size_t sbase = ((size_t)(b * 4096 + n) * 8 + h) * 64 + blk * 32 + ii;
    float v1 = src[sbase];
    float v2 = src[sbase + 16];
    size_t dbase = ((size_t)((b * 8 + h) * 4096 + n)) * 64 + blk * 32 + ii;
    dst[dbase]      = __float2half((v1 * cs - v2 * sn) * qscale);
    dst[dbase + 16] = __float2half((v2 * cs + v1 * sn) * qscale);
}

// ---------------------------------------------------------------------------
// V: fp32 [b,m,(h,d)] -> fp16 transposed [b,h,d,m]
// ---------------------------------------------------------------------------
__global__ __launch_bounds__(256) void vtrans_kernel(
    const float* __restrict__ V, uint32_t* __restrict__ Vt)
{
    const int m0 = blockIdx.x * 64;
    const int h  = blockIdx.y;
    const int b  = blockIdx.z;
    const int t  = threadIdx.x;
    __shared__ float S[64][65];
#pragma unroll
    for (int i = 0; i < 16; ++i) {
        int e = i * 256 + t;
        int m = e >> 6, d = e & 63;
        S[m][d] = V[((size_t)(b * 4096 + m0 + m)) * 512 + h * 64 + d];
    }
    __syncthreads();
#pragma unroll
    for (int i = 0; i < 8; ++i) {
        int e = i * 256 + t;
        int d = e >> 5, mm = e & 31;
        uint32_t v = pack_h2(S[2 * mm][d], S[2 * mm + 1][d]);
        Vt[((size_t)((b * 8 + h) * 64 + d)) * 2048 + (m0 >> 1) + mm] = v;
    }
}

// ---------------------------------------------------------------------------
// Flash attention, ldmatrix fragments, 2-stage cp.async K/V pipeline,
// fused hi/lo fp16 output split.
// ---------------------------------------------------------------------------
__global__ __launch_bounds__(256) void attn_mma_kernel(
    const uint32_t* __restrict__ Qh, const uint32_t* __restrict__ Kh,
    const uint32_t* __restrict__ Vt, const uint32_t* __restrict__ Mb,
    uint32_t* __restrict__ Oh, uint32_t* __restrict__ Ol)
{
    const int b = blockIdx.z, h = blockIdx.y;
    const int q0 = blockIdx.x * 128;
    const int t = threadIdx.x, w = t >> 5, lane = t & 31;
    const int qr = lane >> 2, qc = lane & 3;

    __shared__ uint32_t Ks[2][64 * 36];
    __shared__ uint32_t Vs[2][64 * 36];

    const size_t bh = (size_t)(b * 8 + h);
    const int n0 = q0 + w * 16 + qr;
    const int n1 = n0 + 8;

    const uint32_t lm_off = (((lane & 7) * 36 + (lane >> 3) * 4)) * 4;
    const uint32_t ks_b = smem_u32(Ks) + lm_off;
    const uint32_t vs_b = smem_u32(Vs) + lm_off;
    const uint32_t ks_st = smem_u32(Ks);
    const uint32_t vs_st = smem_u32(Vs);

    const uint32_t* Kg = Kh + bh * SEQ_M * 32;
    const uint32_t* Vg = Vt + bh * HDIM * 2048;

    auto issue = [&](int mt, int st) {
        const int mk = mt * 64;
        const int seg = (t & 7) * 4;
#pragma unroll
        for (int i = 0; i < 2; ++i) {
            int row = i * 32 + (t >> 3);
            uint32_t so = (st * 2304 + row * 36 + seg) * 4;
            cp16(ks_st + so, &Kg[(size_t)(mk + row) * 32 + seg]);
            cp16(vs_st + so, &Vg[(size_t)row * 2048 + (mk >> 1) + seg]);
        }
        cp_commit();
    };

    uint32_t qa[4][4];
    {
        const uint32_t* Qb = Qh + (bh * 4096 + q0 + (size_t)w * 16) * 32;
#pragma unroll
        for (int kc = 0; kc < 4; ++kc) {
            qa[kc][0] = Qb[qr * 32 + kc * 8 + qc];
            qa[kc][1] = Qb[(qr + 8) * 32 + kc * 8 + qc];
            qa[kc][2] = Qb[qr * 32 + kc * 8 + qc + 4];
            qa[kc][3] = Qb[(qr + 8) * 32 + kc * 8 + qc + 4];
        }
    }

    issue(0, 0);
    issue(1, 1);

    float o[8][4];
#pragma unroll
    for (int j = 0; j < 8; ++j)
#pragma unroll
        for (int k = 0; k < 4; ++k) o[j][k] = 0.f;
    float m0r = -1e30f, m1r = -1e30f, l0 = 0.f, l1 = 0.f;

    for (int mt = 0; mt < SEQ_M / 64; ++mt) {
        const int mk = mt * 64;
        const int wz = mk >> 5;
        uint32_t ma0 = Mb[((size_t)(b * 128 + wz)) * 4096 + n0];
        uint32_t ma1 = Mb[((size_t)(b * 128 + wz + 1)) * 4096 + n0];
        uint32_t mb0 = Mb[((size_t)(b * 128 + wz)) * 4096 + n1];
        uint32_t mb1 = Mb[((size_t)(b * 128 + wz + 1)) * 4096 + n1];

        if (mt < SEQ_M / 64 - 1) cp_wait1(); else cp_wait0();
        __syncthreads();

        const uint32_t st_off = (mt & 1) * 2304 * 4;
        const uint32_t ksb = ks_b + st_off;
        const uint32_t vsb = vs_b + st_off;

        // ---- scores ----
        float c[8][4];
#pragma unroll
        for (int j = 0; j < 8; ++j) {
            c[j][0] = c[j][1] = c[j][2] = c[j][3] = 0.f;
            uint32_t k1[4], k2[4];
            uint32_t ka = ksb + j * 8 * 36 * 4;
            ldsm_x4(k1, ka);
            ldsm_x4(k2, ka + 64);
            mma_f16(c[j], qa[0], k1[0], k1[1]);
            mma_f16(c[j], qa[1], k1[2], k1[3]);
            mma_f16(c[j], qa[2], k2[0], k2[1]);
            mma_f16(c[j], qa[3], k2[2], k2[3]);
        }
        // ---- mask + row max ----
        float rx0 = -1e30f, rx1 = -1e30f;
#pragma unroll
        for (int j = 0; j < 8; ++j) {
            int bi = j * 8 + qc * 2;
            uint32_t w0 = (bi < 32) ? ma0 : ma1;
            uint32_t w1 = (bi < 32) ? mb0 : mb1;
            int sh = bi & 31;
            if ((w0 >> sh) & 1u)       c[j][0] = -1e30f;
            if ((w0 >> (sh + 1)) & 1u) c[j][1] = -1e30f;
            if ((w1 >> sh) & 1u)       c[j][2] = -1e30f;
            if ((w1 >> (sh + 1)) & 1u) c[j][3] = -1e30f;
            rx0 = fmaxf(rx0, fmaxf(c[j][0], c[j][1]));
            rx1 = fmaxf(rx1, fmaxf(c[j][2], c[j][3]));
        }
        rx0 = fmaxf(rx0, __shfl_xor_sync(0xffffffffu, rx0, 1));
        rx0 = fmaxf(rx0, __shfl_xor_sync(0xffffffffu, rx0, 2));
        rx1 = fmaxf(rx1, __shfl_xor_sync(0xffffffffu, rx1, 1));
        rx1 = fmaxf(rx1, __shfl_xor_sync(0xffffffffu, rx1, 2));
        float mn0 = fmaxf(m0r, rx0), mn1 = fmaxf(m1r, rx1);
        float cr0 = ex2f(m0r - mn0), cr1 = ex2f(m1r - mn1);
        m0r = mn0; m1r = mn1;
        l0 *= cr0; l1 *= cr1;
#pragma unroll
        for (int j = 0; j < 8; ++j) {
            o[j][0] *= cr0; o[j][1] *= cr0; o[j][2] *= cr1; o[j][3] *= cr1;
        }
#pragma unroll
        for (int j = 0; j < 8; ++j) {
            c[j][0] = ex2f(c[j][0] - m0r); c[j][1] = ex2f(c[j][1] - m0r);
            c[j][2] = ex2f(c[j][2] - m1r); c[j][3] = ex2f(c[j][3] - m1r);
            l0 += c[j][0] + c[j][1];
            l1 += c[j][2] + c[j][3];
        }
        // ---- P fragments, then O += P V ----
        uint32_t pa[4][4];
#pragma unroll
        for (int kc = 0; kc < 4; ++kc) {
            pa[kc][0] = pack_h2(c[2 * kc][0], c[2 * kc][1]);
            pa[kc][1] = pack_h2(c[2 * kc][2], c[2 * kc][3]);
            pa[kc][2] = pack_h2(c[2 * kc + 1][0], c[2 * kc + 1][1]);
            pa[kc][3] = pack_h2(c[2 * kc + 1][2], c[2 * kc + 1][3]);
        }
#pragma unroll
        for (int nd = 0; nd < 8; ++nd) {
            uint32_t v1[4], v2[4];
            uint32_t va = vsb + nd * 8 * 36 * 4;
            ldsm_x4(v1, va);
            ldsm_x4(v2, va + 64);
            mma_f16(o[nd], pa[0], v1[0], v1[1]);
            mma_f16(o[nd], pa[1], v1[2], v1[3]);
            mma_f16(o[nd], pa[2], v2[0], v2[1]);
            mma_f16(o[nd], pa[3], v2[2], v2[3]);
        }
        __syncthreads();
        if (mt + 2 < SEQ_M / 64) issue(mt + 2, mt & 1);
    }

    l0 += __shfl_xor_sync(0xffffffffu, l0, 1);
    l0 += __shfl_xor_sync(0xffffffffu, l0, 2);
    l1 += __shfl_xor_sync(0xffffffffu, l1, 1);
    l1 += __shfl_xor_sync(0xffffffffu, l1, 2);
    float i0 = 1.f / fmaxf(l0, 1e-30f);
    float i1 = 1.f / fmaxf(l1, 1e-30f);
#pragma unroll
    for (int j = 0; j < 8; ++j) {
        int colw = h * 32 + j * 4 + qc;
        float v0 = o[j][0] * i0, v1 = o[j][1] * i0;
        float v2 = o[j][2] * i1, v3 = o[j][3] * i1;
        __half h0 = __float2half(v0), h1 = __float2half(v1);
        __half h2 = __float2half(v2), h3 = __float2half(v3);
        Oh[(size_t)n0 * 256 + (size_t)b * 4096 * 256 + colw] =
            ((uint32_t)__half_as_ushort(h1) << 16) | __half_as_ushort(h0);
        Ol[(size_t)n0 * 256 + (size_t)b * 4096 * 256 + colw] =
            pack_h2(v0 - __half2float(h0), v1 - __half2float(h1));
        Oh[(size_t)n1 * 256 + (size_t)b * 4096 * 256 + colw] =
            ((uint32_t)__half_as_ushort(h3) << 16) | __half_as_ushort(h2);
        Ol[(size_t)n1 * 256 + (size_t)b * 4096 * 256 + colw] =
            pack_h2(v2 - __half2float(h2), v3 - __half2float(h3));
    }
}

// ---------------------------------------------------------------------------
// Launch
// ---------------------------------------------------------------------------
extern "C" void kernel_launch(void* const* d_in, const int* in_sizes, int n_in,
                              void* d_out, int out_size)
{
    const float* x       = (const float*)d_in[0];
    const float* context = (const float*)d_in[1];
    const int*   pos_x   = (const int*)d_in[2];
    const int*   pos_ctx = (const int*)d_in[3];
    const unsigned char* mask = (const unsigned char*)d_in[4];
    const float* Wq = (const float*)d_in[5];
    const float* bq = (const float*)d_in[6];
    const float* Wk = (const float*)d_in[7];
    const float* bk = (const float*)d_in[8];
    const float* Wv = (const float*)d_in[9];
    const float* bv = (const float*)d_in[10];
    const float* Wo = (const float*)d_in[11];
    const float* bo = (const float*)d_in[12];
    float* out = (float*)d_out;

    float *qp, *kp, *vp;
    __half *qh, *kh;
    uint32_t *vt, *mb;
    __half *xh, *xl, *chh, *cl, *wth, *wtl;
    cudaGetSymbolAddress((void**)&qp, g_Q);
    cudaGetSymbolAddress((void**)&kp, g_K);
    cudaGetSymbolAddress((void**)&vp, g_V);
    cudaGetSymbolAddress((void**)&qh, g_Qh);
    cudaGetSymbolAddress((void**)&kh, g_Kh);
    cudaGetSymbolAddress((void**)&vt, g_Vt);
    cudaGetSymbolAddress((void**)&mb, g_Mbits);
    cudaGetSymbolAddress((void**)&xh, g_Xh);
    cudaGetSymbolAddress((void**)&xl, g_Xl);
    cudaGetSymbolAddress((void**)&chh, g_Ch);
    cudaGetSymbolAddress((void**)&cl, g_Cl);
    cudaGetSymbolAddress((void**)&wth, g_Wth);
    cudaGetSymbolAddress((void**)&wtl, g_Wtl);

    const int WSZ2 = DIM_C * DIM_C / 2;
    const int GEMM_SMEM = 2 * GSTAGE_WORDS * 4;   // 80 KB
    cudaFuncSetAttribute(gemm_mma_kernel,
                         cudaFuncAttributeMaxDynamicSharedMemorySize, GEMM_SMEM);

    // launch order: gemm_mma is the 4th launch (profiling target)
    dim3 wgrid(8, 8, 4);
    wsplit4_kernel<<<wgrid, 256>>>(Wq, Wk, Wv, Wo, (uint32_t*)wth, (uint32_t*)wtl);

    const int n4 = BATCH * SEQ_N * DIM_C / 4;
    dim3 sgrid(n4 / 256, 2);
    split2_kernel<<<sgrid, 256>>>((const float4*)x, (const float4*)context,
                                  (uint2*)xh, (uint2*)xl, (uint2*)chh, (uint2*)cl, n4);

    detect_mask_kernel<<<1, 256>>>((const uint32_t*)mask);

    dim3 ggrid(DIM_C / 128, (BATCH * SEQ_N) / 128);   // (4, 64)
    gemm_mma_kernel<<<ggrid, 256, GEMM_SMEM>>>(
        (const uint32_t*)xh, (const uint32_t*)xl,
        (const uint32_t*)wth + 0 * WSZ2, (const uint32_t*)wtl + 0 * WSZ2, bq, qp);

    pack_mask_kernel<<<BATCH * SEQ_N, 128>>>(mask, mb);

    gemm_mma_kernel<<<ggrid, 256, GEMM_SMEM>>>(
        (const uint32_t*)chh, (const uint32_t*)cl,
        (const uint32_t*)wth + 1 * WSZ2, (const uint32_t*)wtl + 1 * WSZ2, bk, kp);
    gemm_mma_kernel<<<ggrid, 256, GEMM_SMEM>>>(
        (const uint32_t*)chh, (const uint32_t*)cl,
        (const uint32_t*)wth + 2 * WSZ2, (const uint32_t*)wtl + 2 * WSZ2, bv, vp);

    const int rope_total = BATCH * SEQ_N * HEADS * 32;
    const float qscale = 0.125f * 1.4426950408889634f;
    rope2d_h_kernel<<<(rope_total + 255) / 256, 256>>>(qp, qh, pos_x, qscale, rope_total);
    rope2d_h_kernel<<<(rope_total + 255) / 256, 256>>>(kp, kh, pos_ctx, 1.0f, rope_total);

    dim3 vgrid(SEQ_M / 64, HEADS, BATCH);
    vtrans_kernel<<<vgrid, 256>>>(vp, vt);

    dim3 agrid(SEQ_N / 128, HEADS, BATCH);
    attn_mma_kernel<<<agrid, 256>>>((const uint32_t*)qh, (const uint32_t*)kh,
                                    vt, mb, (uint32_t*)xh, (uint32_t*)xl);

    gemm_mma_kernel<<<ggrid, 256, GEMM_SMEM>>>(
        (const uint32_t*)xh, (const uint32_t*)xl,
        (const uint32_t*)wth + 3 * WSZ2, (const uint32_t*)wtl + 3 * WSZ2, bo, out);
}

// round 7
// speedup vs baseline: 7.1452x; 1.0035x over previous
#include <cuda_runtime.h>
#include <cuda_fp16.h>
#include <cstdint>

#define BATCH 2
#define SEQ_N 4096
#define SEQ_M 4096
#define DIM_C 512
#define HEADS 8
#define HDIM  64

// ---------------------------------------------------------------------------
// Scratch
// ---------------------------------------------------------------------------
__device__ float g_Q[BATCH * SEQ_N * DIM_C];
__device__ float g_K[BATCH * SEQ_M * DIM_C];
__device__ float g_V[BATCH * SEQ_M * DIM_C];
__device__ __half g_Qh[BATCH * HEADS * SEQ_N * HDIM];
__device__ __half g_Kh[BATCH * HEADS * SEQ_M * HDIM];
__device__ __half g_Vt[BATCH * HEADS * HDIM * SEQ_M];
__device__ uint32_t g_Mbits[BATCH * 128 * SEQ_N];
__device__ int g_maskBool;
__device__ __half g_Xh[BATCH * SEQ_N * DIM_C];
__device__ __half g_Xl[BATCH * SEQ_N * DIM_C];
__device__ __half g_Ch[BATCH * SEQ_M * DIM_C];
__device__ __half g_Cl[BATCH * SEQ_M * DIM_C];
__device__ __half g_Wth[4 * DIM_C * DIM_C];   // transposed [n][k]
__device__ __half g_Wtl[4 * DIM_C * DIM_C];

// ---------------------------------------------------------------------------
// helpers
// ---------------------------------------------------------------------------
__device__ __forceinline__ float ex2f(float x) {
    float y; asm("ex2.approx.ftz.f32 %0, %1;" : "=f"(y) : "f"(x)); return y;
}
__device__ __forceinline__ uint32_t pack_h2(float lo, float hi) {
    uint32_t r; asm("cvt.rn.f16x2.f32 %0, %1, %2;" : "=r"(r) : "f"(hi), "f"(lo)); return r;
}
__device__ __forceinline__ void mma_f16(float c[4], const uint32_t a[4],
                                        uint32_t b0, uint32_t b1) {
    asm volatile(
        "mma.sync.aligned.m16n8k16.row.col.f32.f16.f16.f32 "
        "{%0,%1,%2,%3}, {%4,%5,%6,%7}, {%8,%9}, {%0,%1,%2,%3};"
        : "+f"(c[0]), "+f"(c[1]), "+f"(c[2]), "+f"(c[3])
        : "r"(a[0]), "r"(a[1]), "r"(a[2]), "r"(a[3]), "r"(b0), "r"(b1));
}
__device__ __forceinline__ void ldsm_x4(uint32_t r[4], uint32_t addr) {
    asm volatile("ldmatrix.sync.aligned.m8n8.x4.shared.b16 {%0,%1,%2,%3}, [%4];"
                 : "=r"(r[0]), "=r"(r[1]), "=r"(r[2]), "=r"(r[3]) : "r"(addr));
}
__device__ __forceinline__ uint32_t smem_u32(const void* p) {
    return (uint32_t)__cvta_generic_to_shared(p);
}
__device__ __forceinline__ void cp16(uint32_t smem_dst, const void* gsrc) {
    asm volatile("cp.async.cg.shared.global [%0], [%1], 16;" ::
                 "r"(smem_dst), "l"(gsrc));
}
__device__ __forceinline__ void cp_commit() {
    asm volatile("cp.async.commit_group;");
}
__device__ __forceinline__ void cp_wait1() {
    asm volatile("cp.async.wait_group 1;");
}
__device__ __forceinline__ void cp_wait0() {
    asm volatile("cp.async.wait_group 0;");
}

// ---------------------------------------------------------------------------
// Mask dtype detection + packing (verified)
// ---------------------------------------------------------------------------
__global__ void detect_mask_kernel(const uint32_t* __restrict__ m)
{
    __shared__ int found;
    if (threadIdx.x == 0) found = 0;
    __syncthreads();
    uint32_t v = m[threadIdx.x] | m[threadIdx.x + 256] |
                 m[threadIdx.x + 512] | m[threadIdx.x + 768];
    if (v > 1u) atomicOr(&found, 1);
    __syncthreads();
    if (threadIdx.x == 0) g_maskBool = found;
}

__global__ __launch_bounds__(128) void pack_mask_kernel(
    const unsigned char* __restrict__ mraw, uint32_t* __restrict__ out)
{
    const int bn = blockIdx.x;
    const int w  = threadIdx.x;
    const int b  = bn >> 12;
    const int n  = bn & 4095;
    uint32_t bits = 0;
    if (g_maskBool) {
        const uint32_t* p = (const uint32_t*)(mraw + (size_t)bn * 4096) + w * 8;
#pragma unroll
        for (int i = 0; i < 8; ++i) {
            uint32_t v = p[i];
#pragma unroll
            for (int j = 0; j < 4; ++j)
                if ((v >> (j * 8)) & 0xFFu) bits |= 1u << (i * 4 + j);
        }
    } else {
        const int* p = (const int*)mraw + (size_t)bn * 4096 + w * 32;
#pragma unroll
        for (int i = 0; i < 32; ++i)
            if (p[i] != 0) bits |= 1u << i;
    }
    out[((size_t)(b * 128 + w)) * 4096 + n] = bits;
}

// ---------------------------------------------------------------------------
// All 4 weights: transpose + fp16 split in one launch (grid z = weight id)
// ---------------------------------------------------------------------------
__global__ __launch_bounds__(256) void wsplit4_kernel(
    const float* __restrict__ W0, const float* __restrict__ W1,
    const float* __restrict__ W2, const float* __restrict__ W3,
    uint32_t* __restrict__ Wth, uint32_t* __restrict__ Wtl)
{
    const int z = blockIdx.z;
    const float* W = (z == 0) ? W0 : (z == 1) ? W1 : (z == 2) ? W2 : W3;
    uint32_t* oh = Wth + (size_t)z * (DIM_C * DIM_C / 2);
    uint32_t* ol = Wtl + (size_t)z * (DIM_C * DIM_C / 2);

    const int n0 = blockIdx.x * 64;
    const int k0 = blockIdx.y * 64;
    const int t  = threadIdx.x;
    __shared__ float S[64][65];
#pragma unroll
    for (int i = 0; i < 16; ++i) {
        int e = i * 256 + t;
        int r = e >> 6, c = e & 63;
        S[r][c] = W[(size_t)(k0 + r) * 512 + n0 + c];
    }
    __syncthreads();
#pragma unroll
    for (int i = 0; i < 8; ++i) {
        int e = i * 256 + t;
        int n = e >> 5, kw = e & 31;
        float v0 = S[2 * kw][n], v1 = S[2 * kw + 1][n];
        __half h0 = __float2half(v0), h1 = __float2half(v1);
        float r0 = v0 - __half2float(h0), r1 = v1 - __half2float(h1);
        size_t dst = (size_t)(n0 + n) * 256 + (k0 >> 1) + kw;
        oh[dst] = ((uint32_t)__half_as_ushort(h1) << 16) | __half_as_ushort(h0);
        ol[dst] = pack_h2(r0, r1);
    }
}

// ---------------------------------------------------------------------------
// x and context fp16 splits in one launch (grid y = which input)
// ---------------------------------------------------------------------------
__global__ void split2_kernel(const float4* __restrict__ x, const float4* __restrict__ ctx,
                              uint2* __restrict__ xh, uint2* __restrict__ xl,
                              uint2* __restrict__ ch, uint2* __restrict__ cl, int n4)
{
    int i = blockIdx.x * blockDim.x + threadIdx.x;
    if (i >= n4) return;
    const float4* s = blockIdx.y ? ctx : x;
    uint2* oh = blockIdx.y ? ch : xh;
    uint2* ol = blockIdx.y ? cl : xl;
    float4 v = s[i];
    __half hx = __float2half(v.x), hy = __float2half(v.y);
    __half hz = __float2half(v.z), hw = __float2half(v.w);
    uint2 h, l;
    h.x = ((uint32_t)__half_as_ushort(hy) << 16) | __half_as_ushort(hx);
    h.y = ((uint32_t)__half_as_ushort(hw) << 16) | __half_as_ushort(hz);
    l.x = pack_h2(v.x - __half2float(hx), v.y - __half2float(hy));
    l.y = pack_h2(v.z - __half2float(hz), v.w - __half2float(hw));
    oh[i] = h;
    ol[i] = l;
}

// ---------------------------------------------------------------------------
// Tensor-core GEMM, fp16 split (3-product), ldmatrix fragments,
// 2-stage cp.async pipeline, 4-way interleaved mma chains.
// ---------------------------------------------------------------------------
#define GSTAGE_WORDS (4 * 128 * 20)
__global__ __launch_bounds__(256) void gemm_mma_kernel(
    const uint32_t* __restrict__ Ah, const uint32_t* __restrict__ Al,
    const uint32_t* __restrict__ Wth, const uint32_t* __restrict__ Wtl,
    const float* __restrict__ bias, float* __restrict__ Y)
{
    extern __shared__ uint32_t sm[];
    const int row0 = blockIdx.y * 128;
    const int col0 = blockIdx.x * 128;
    const int t = threadIdx.x, w = t >> 5, lane = t & 31;
    const int wm = w & 3, wn = w >> 2;
    const int qr = lane >> 2, qc = lane & 3;

    const uint32_t smb = smem_u32(sm);

    float acc[2][8][4];
#pragma unroll
    for (int mt = 0; mt < 2; ++mt)
#pragma unroll
        for (int n = 0; n < 8; ++n)
#pragma unroll
            for (int k = 0; k < 4; ++k) acc[mt][n][k] = 0.f;

    const int a_row = wm * 32 + (lane & 7) + ((lane >> 3) & 1) * 8;
    const int a_wrd = (lane >> 4) * 4;
    const uint32_t ah_o = (0 * 2560 + a_row * 20 + a_wrd) * 4;
    const uint32_t al_o = (1 * 2560 + a_row * 20 + a_wrd) * 4;
    const int b_row = wn * 64 + (lane & 7);
    const int b_wrd = (lane >> 3) * 4;
    const uint32_t wh_o = (2 * 2560 + b_row * 20 + b_wrd) * 4;
    const uint32_t wl_o = (3 * 2560 + b_row * 20 + b_wrd) * 4;

    const int ld_seg = (t & 3) * 4;

    auto issue = [&](int ch, int st) {
        const int kw = ch * 16;
        const uint32_t sb = smb + st * GSTAGE_WORDS * 4;
#pragma unroll
        for (int i = 0; i < 2; ++i) {
            int row = i * 64 + (t >> 2);
            size_t ga = (size_t)(row0 + row) * 256 + kw + ld_seg;
            size_t gw = (size_t)(col0 + row) * 256 + kw + ld_seg;
            uint32_t so = (row * 20 + ld_seg) * 4;
            cp16(sb + 0 * 2560 * 4 + so, &Ah[ga]);
            cp16(sb + 1 * 2560 * 4 + so, &Al[ga]);
            cp16(sb + 2 * 2560 * 4 + so, &Wth[gw]);
            cp16(sb + 3 * 2560 * 4 + so, &Wtl[gw]);
        }
        cp_commit();
    };

    issue(0, 0);
    issue(1, 1);

    for (int ch = 0; ch < 16; ++ch) {
        if (ch < 15) cp_wait1(); else cp_wait0();
        __syncthreads();

        const uint32_t sb = smb + (ch & 1) * GSTAGE_WORDS * 4;
        uint32_t ahi[2][2][4], alo[2][2][4];
#pragma unroll
        for (int mt = 0; mt < 2; ++mt)
#pragma unroll
            for (int kc = 0; kc < 2; ++kc) {
                ldsm_x4(ahi[mt][kc], sb + ah_o + (mt * 16 * 20 + kc * 8) * 4);
                ldsm_x4(alo[mt][kc], sb + al_o + (mt * 16 * 20 + kc * 8) * 4);
            }
        // n processed in pairs -> 4 independent accumulator chains per step
#pragma unroll
        for (int np = 0; np < 4; ++np) {
            const int n0 = 2 * np, n1 = 2 * np + 1;
            uint32_t bh0[4], bh1[4], bl0[4], bl1[4];
            ldsm_x4(bh0, sb + wh_o + n0 * 8 * 20 * 4);
            ldsm_x4(bh1, sb + wh_o + n1 * 8 * 20 * 4);
            ldsm_x4(bl0, sb + wl_o + n0 * 8 * 20 * 4);
            ldsm_x4(bl1, sb + wl_o + n1 * 8 * 20 * 4);
            // s0: ahi x bh, kc0
            mma_f16(acc[0][n0], ahi[0][0], bh0[0], bh0[1]);
            mma_f16(acc[1][n0], ahi[1][0], bh0[0], bh0[1]);
            mma_f16(acc[0][n1], ahi[0][0], bh1[0], bh1[1]);
            mma_f16(acc[1][n1], ahi[1][0], bh1[0], bh1[1]);
            // s1: ahi x bh, kc1
            mma_f16(acc[0][n0], ahi[0][1], bh0[2], bh0[3]);
            mma_f16(acc[1][n0], ahi[1][1], bh0[2], bh0[3]);
            mma_f16(acc[0][n1], ahi[0][1], bh1[2], bh1[3]);
            mma_f16(acc[1][n1], ahi[1][1], bh1[2], bh1[3]);
            // s2: alo x bh, kc0
            mma_f16(acc[0][n0], alo[0][0], bh0[0], bh0[1]);
            mma_f16(acc[1][n0], alo[1][0], bh0[0], bh0[1]);
            mma_f16(acc[0][n1], alo[0][0], bh1[0], bh1[1]);
            mma_f16(acc[1][n1], alo[1][0], bh1[0], bh1[1]);
            // s3: alo x bh, kc1
            mma_f16(acc[0][n0], alo[0][1], bh0[2], bh0[3]);
            mma_f16(acc[1][n0], alo[1][1], bh0[2], bh0[3]);
            mma_f16(acc[0][n1], alo[0][1], bh1[2], bh1[3]);
            mma_f16(acc[1][n1], alo[1][1], bh1[2], bh1[3]);
            // s4: ahi x bl, kc0
            mma_f16(acc[0][n0], ahi[0][0], bl0[0], bl0[1]);
            mma_f16(acc[1][n0], ahi[1][0], bl0[0], bl0[1]);
            mma_f16(acc[0][n1], ahi[0][0], bl1[0], bl1[1]);
            mma_f16(acc[1][n1], ahi[1][0], bl1[0], bl1[1]);
            // s5: ahi x bl, kc1
            mma_f16(acc[0][n0], ahi[0][1], bl0[2], bl0[3]);
            mma_f16(acc[1][n0], ahi[1][1], bl0[2], bl0[3]);
            mma_f16(acc[0][n1], ahi[0][1], bl1[2], bl1[3]);
            mma_f16(acc[1][n1], ahi[1][1], bl1[2], bl1[3]);
        }
        __syncthreads();
        if (ch + 2 < 16) issue(ch + 2, ch & 1);
    }

#pragma unroll
    for (int mt = 0; mt < 2; ++mt)
#pragma unroll
        for (int n = 0; n < 8; ++n) {
            int row = row0 + wm * 32 + mt * 16 + qr;
            int col = col0 + wn * 64 + n * 8 + qc * 2;
            float2 bi = *(const float2*)&bias[col];
            float2 v0 = make_float2(acc[mt][n][0] + bi.x, acc[mt][n][1] + bi.y);
            float2 v1 = make_float2(acc[mt][n][2] + bi.x, acc[mt][n][3] + bi.y);
            *(float2*)&Y[(size_t)row * 512 + col] = v0;
            *(float2*)&Y[(size_t)(row + 8) * 512 + col] = v1;
        }
}

// ---------------------------------------------------------------------------
// RoPE 2D: fp32 [b,n,h,64] -> fp16 [b,h,n,64], scale folded in.
// ---------------------------------------------------------------------------
__global__ void rope2d_h_kernel(const float* __restrict__ src, __half* __restrict__ dst,
                                const int* __restrict__ pos, float qscale, int total)
{
    int idx = blockIdx.x * blockDim.x + threadIdx.x;
    if (idx >= total) return;
    int pair = idx & 31;
    int h    = (idx >> 5) & 7;
    int n    = (idx >> 8) & 4095;
    int b    = idx >> 20;
    int blk  = pair >> 4;
    int ii   = pair & 15;

    float invf = exp2f(-(float)ii * 0.41524101186092864f);
    int p = pos[((size_t)(b * 4096 + n)) * 2 + blk];
    float ang = (float)p * invf;
    float sn, cs;
    sincosf(ang, &sn, &cs);

    size_t sbase = ((size_t)(b * 4096 + n) * 8 + h) * 64 + blk * 32 + ii;
    float v1 = src[sbase];
    float v2 = src[sbase + 16];
    size_t dbase = ((size_t)((b * 8 + h) * 4096 + n)) * 64 + blk * 32 + ii;
    dst[dbase]      = __float2half((v1 * cs - v2 * sn) * qscale);
    dst[dbase + 16] = __float2half((v2 * cs + v1 * sn) * qscale);
}

// ---------------------------------------------------------------------------
// V: fp32 [b,m,(h,d)] -> fp16 transposed [b,h,d,m]
// ---------------------------------------------------------------------------
__global__ __launch_bounds__(256) void vtrans_kernel(
    const float* __restrict__ V, uint32_t* __restrict__ Vt)
{
    const int m0 = blockIdx.x * 64;
    const int h  = blockIdx.y;
    const int b  = blockIdx.z;
    const int t  = threadIdx.x;
    __shared__ float S[64][65];
#pragma unroll
    for (int i = 0; i < 16; ++i) {
        int e = i * 256 + t;
        int m = e >> 6, d = e & 63;
        S[m][d] = V[((size_t)(b * 4096 + m0 + m)) * 512 + h * 64 + d];
    }
    __syncthreads();
#pragma unroll
    for (int i = 0; i < 8; ++i) {
        int e = i * 256 + t;
        int d = e >> 5, mm = e & 31;
        uint32_t v = pack_h2(S[2 * mm][d], S[2 * mm + 1][d]);
        Vt[((size_t)((b * 8 + h) * 64 + d)) * 2048 + (m0 >> 1) + mm] = v;
    }
}

// ---------------------------------------------------------------------------
// Flash attention: 4-way interleaved mma chains, cp.async K/V pipeline,
// fused hi/lo fp16 output split.
// ---------------------------------------------------------------------------
__global__ __launch_bounds__(256) void attn_mma_kernel(
    const uint32_t* __restrict__ Qh, const uint32_t* __restrict__ Kh,
    const uint32_t* __restrict__ Vt, const uint32_t* __restrict__ Mb,
    uint32_t* __restrict__ Oh, uint32_t* __restrict__ Ol)
{
    const int b = blockIdx.z, h = blockIdx.y;
    const int q0 = blockIdx.x * 128;
    const int t = threadIdx.x, w = t >> 5, lane = t & 31;
    const int qr = lane >> 2, qc = lane & 3;

    __shared__ uint32_t Ks[2][64 * 36];
    __shared__ uint32_t Vs[2][64 * 36];

    const size_t bh = (size_t)(b * 8 + h);
    const int n0 = q0 + w * 16 + qr;
    const int n1 = n0 + 8;

    const uint32_t lm_off = (((lane & 7) * 36 + (lane >> 3) * 4)) * 4;
    const uint32_t ks_b = smem_u32(Ks) + lm_off;
    const uint32_t vs_b = smem_u32(Vs) + lm_off;
    const uint32_t ks_st = smem_u32(Ks);
    const uint32_t vs_st = smem_u32(Vs);

    const uint32_t* Kg = Kh + bh * SEQ_M * 32;
    const uint32_t* Vg = Vt + bh * HDIM * 2048;

    auto issue = [&](int mt, int st) {
        const int mk = mt * 64;
        const int seg = (t & 7) * 4;
#pragma unroll
        for (int i = 0; i < 2; ++i) {
            int row = i * 32 + (t >> 3);
            uint32_t so = (st * 2304 + row * 36 + seg) * 4;
            cp16(ks_st + so, &Kg[(size_t)(mk + row) * 32 + seg]);
            cp16(vs_st + so, &Vg[(size_t)row * 2048 + (mk >> 1) + seg]);
        }
        cp_commit();
    };

    uint32_t qa[4][4];
    {
        const uint32_t* Qb = Qh + (bh * 4096 + q0 + (size_t)w * 16) * 32;
#pragma unroll
        for (int kc = 0; kc < 4; ++kc) {
            qa[kc][0] = Qb[qr * 32 + kc * 8 + qc];
            qa[kc][1] = Qb[(qr + 8) * 32 + kc * 8 + qc];
            qa[kc][2] = Qb[qr * 32 + kc * 8 + qc + 4];
            qa[kc][3] = Qb[(qr + 8) * 32 + kc * 8 + qc + 4];
        }
    }

    issue(0, 0);
    issue(1, 1);

    float o[8][4];
#pragma unroll
    for (int j = 0; j < 8; ++j)
#pragma unroll
        for (int k = 0; k < 4; ++k) o[j][k] = 0.f;
    float m0r = -1e30f, m1r = -1e30f, l0 = 0.f, l1 = 0.f;

    for (int mt = 0; mt < SEQ_M / 64; ++mt) {
        const int mk = mt * 64;
        const int wz = mk >> 5;
        uint32_t ma0 = Mb[((size_t)(b * 128 + wz)) * 4096 + n0];
        uint32_t ma1 = Mb[((size_t)(b * 128 + wz + 1)) * 4096 + n0];
        uint32_t mb0 = Mb[((size_t)(b * 128 + wz)) * 4096 + n1];
        uint32_t mb1 = Mb[((size_t)(b * 128 + wz + 1)) * 4096 + n1];

        if (mt < SEQ_M / 64 - 1) cp_wait1(); else cp_wait0();
        __syncthreads();

        const uint32_t st_off = (mt & 1) * 2304 * 4;
        const uint32_t ksb = ks_b + st_off;
        const uint32_t vsb = vs_b + st_off;

        // ---- scores: j in groups of 4 -> 4 independent chains ----
        float c[8][4];
#pragma unroll
        for (int jg = 0; jg < 8; jg += 4) {
            uint32_t kA[4][4], kB[4][4];
#pragma unroll
            for (int jj = 0; jj < 4; ++jj) {
                uint32_t ka = ksb + (jg + jj) * 8 * 36 * 4;
                ldsm_x4(kA[jj], ka);
                ldsm_x4(kB[jj], ka + 64);
            }
#pragma unroll
            for (int jj = 0; jj < 4; ++jj) {
                c[jg + jj][0] = c[jg + jj][1] = 0.f;
                c[jg + jj][2] = c[jg + jj][3] = 0.f;
            }
#pragma unroll
            for (int jj = 0; jj < 4; ++jj) mma_f16(c[jg + jj], qa[0], kA[jj][0], kA[jj][1]);
#pragma unroll
            for (int jj = 0; jj < 4; ++jj) mma_f16(c[jg + jj], qa[1], kA[jj][2], kA[jj][3]);
#pragma unroll
            for (int jj = 0; jj < 4; ++jj) mma_f16(c[jg + jj], qa[2], kB[jj][0], kB[jj][1]);
#pragma unroll
            for (int jj = 0; jj < 4; ++jj) mma_f16(c[jg + jj], qa[3], kB[jj][2], kB[jj][3]);
        }
        // ---- mask + row max ----
        float rx0 = -1e30f, rx1 = -1e30f;
#pragma unroll
        for (int j = 0; j < 8; ++j) {
            int bi = j * 8 + qc * 2;
            uint32_t w0 = (bi < 32) ? ma0 : ma1;
            uint32_t w1 = (bi < 32) ? mb0 : mb1;
            int sh = bi & 31;
            if ((w0 >> sh) & 1u)       c[j][0] = -1e30f;
            if ((w0 >> (sh + 1)) & 1u) c[j][1] = -1e30f;
            if ((w1 >> sh) & 1u)       c[j][2] = -1e30f;
            if ((w1 >> (sh + 1)) & 1u) c[j][3] = -1e30f;
            rx0 = fmaxf(rx0, fmaxf(c[j][0], c[j][1]));
            rx1 = fmaxf(rx1, fmaxf(c[j][2], c[j][3]));
        }
        rx0 = fmaxf(rx0, __shfl_xor_sync(0xffffffffu, rx0, 1));
        rx0 = fmaxf(rx0, __shfl_xor_sync(0xffffffffu, rx0, 2));
        rx1 = fmaxf(rx1, __shfl_xor_sync(0xffffffffu, rx1, 1));
        rx1 = fmaxf(rx1, __shfl_xor_sync(0xffffffffu, rx1, 2));
        float mn0 = fmaxf(m0r, rx0), mn1 = fmaxf(m1r, rx1);
        float cr0 = ex2f(m0r - mn0), cr1 = ex2f(m1r - mn1);
        m0r = mn0; m1r = mn1;
        l0 *= cr0; l1 *= cr1;
#pragma unroll
        for (int j = 0; j < 8; ++j) {
            o[j][0] *= cr0; o[j][1] *= cr0; o[j][2] *= cr1; o[j][3] *= cr1;
        }
#pragma unroll
        for (int j = 0; j < 8; ++j) {
            c[j][0] = ex2f(c[j][0] - m0r); c[j][1] = ex2f(c[j][1] - m0r);
            c[j][2] = ex2f(c[j][2] - m1r); c[j][3] = ex2f(c[j][3] - m1r);
            l0 += c[j][0] + c[j][1];
            l1 += c[j][2] + c[j][3];
        }
        // ---- P fragments, then O += P V (nd groups of 4 -> 4 chains) ----
        uint32_t pa[4][4];
#pragma unroll
        for (int kc = 0; kc < 4; ++kc) {
            pa[kc][0] = pack_h2(c[2 * kc][0], c[2 * kc][1]);
            pa[kc][1] = pack_h2(c[2 * kc][2], c[2 * kc][3]);
            pa[kc][2] = pack_h2(c[2 * kc + 1][0], c[2 * kc + 1][1]);
            pa[kc][3] = pack_h2(c[2 * kc + 1][2], c[2 * kc + 1][3]);
        }
#pragma unroll
        for (int ng = 0; ng < 8; ng += 4) {
            uint32_t vA[4][4], vB[4][4];
#pragma unroll
            for (int jj = 0; jj < 4; ++jj) {
                uint32_t va = vsb + (ng + jj) * 8 * 36 * 4;
                ldsm_x4(vA[jj], va);
                ldsm_x4(vB[jj], va + 64);
            }
#pragma unroll
            for (int jj = 0; jj < 4; ++jj) mma_f16(o[ng + jj], pa[0], vA[jj][0], vA[jj][1]);
#pragma unroll
            for (int jj = 0; jj < 4; ++jj) mma_f16(o[ng + jj], pa[1], vA[jj][2], vA[jj][3]);
#pragma unroll
            for (int jj = 0; jj < 4; ++jj) mma_f16(o[ng + jj], pa[2], vB[jj][0], vB[jj][1]);
#pragma unroll
            for (int jj = 0; jj < 4; ++jj) mma_f16(o[ng + jj], pa[3], vB[jj][2], vB[jj][3]);
        }
        __syncthreads();
        if (mt + 2 < SEQ_M / 64) issue(mt + 2, mt & 1);
    }

    l0 += __shfl_xor_sync(0xffffffffu, l0, 1);
    l0 += __shfl_xor_sync(0xffffffffu, l0, 2);
    l1 += __shfl_xor_sync(0xffffffffu, l1, 1);
    l1 += __shfl_xor_sync(0xffffffffu, l1, 2);
    float i0 = 1.f / fmaxf(l0, 1e-30f);
    float i1 = 1.f / fmaxf(l1, 1e-30f);
#pragma unroll
    for (int j = 0; j < 8; ++j) {
        int colw = h * 32 + j * 4 + qc;
        float v0 = o[j][0] * i0, v1 = o[j][1] * i0;
        float v2 = o[j][2] * i1, v3 = o[j][3] * i1;
        __half h0 = __float2half(v0), h1 = __float2half(v1);
        __half h2 = __float2half(v2), h3 = __float2half(v3);
        Oh[(size_t)n0 * 256 + (size_t)b * 4096 * 256 + colw] =
            ((uint32_t)__half_as_ushort(h1) << 16) | __half_as_ushort(h0);
        Ol[(size_t)n0 * 256 + (size_t)b * 4096 * 256 + colw] =
            pack_h2(v0 - __half2float(h0), v1 - __half2float(h1));
        Oh[(size_t)n1 * 256 + (size_t)b * 4096 * 256 + colw] =
            ((uint32_t)__half_as_ushort(h3) << 16) | __half_as_ushort(h2);
        Ol[(size_t)n1 * 256 + (size_t)b * 4096 * 256 + colw] =
            pack_h2(v2 - __half2float(h2), v3 - __half2float(h3));
    }
}

// ---------------------------------------------------------------------------
// Launch
// ---------------------------------------------------------------------------
extern "C" void kernel_launch(void* const* d_in, const int* in_sizes, int n_in,
                              void* d_out, int out_size)
{
    const float* x       = (const float*)d_in[0];
    const float* context = (const float*)d_in[1];
    const int*   pos_x   = (const int*)d_in[2];
    const int*   pos_ctx = (const int*)d_in[3];
    const unsigned char* mask = (const unsigned char*)d_in[4];
    const float* Wq = (const float*)d_in[5];
    const float* bq = (const float*)d_in[6];
    const float* Wk = (const float*)d_in[7];
    const float* bk = (const float*)d_in[8];
    const float* Wv = (const float*)d_in[9];
    const float* bv = (const float*)d_in[10];
    const float* Wo = (const float*)d_in[11];
    const float* bo = (const float*)d_in[12];
    float* out = (float*)d_out;

    float *qp, *kp, *vp;
    __half *qh, *kh;
    uint32_t *vt, *mb;
    __half *xh, *xl, *chh, *cl, *wth, *wtl;
    cudaGetSymbolAddress((void**)&qp, g_Q);
    cudaGetSymbolAddress((void**)&kp, g_K);
    cudaGetSymbolAddress((void**)&vp, g_V);
    cudaGetSymbolAddress((void**)&qh, g_Qh);
    cudaGetSymbolAddress((void**)&kh, g_Kh);
    cudaGetSymbolAddress((void**)&vt, g_Vt);
    cudaGetSymbolAddress((void**)&mb, g_Mbits);
    cudaGetSymbolAddress((void**)&xh, g_Xh);
    cudaGetSymbolAddress((void**)&xl, g_Xl);
    cudaGetSymbolAddress((void**)&chh, g_Ch);
    cudaGetSymbolAddress((void**)&cl, g_Cl);
    cudaGetSymbolAddress((void**)&wth, g_Wth);
    cudaGetSymbolAddress((void**)&wtl, g_Wtl);

    const int WSZ2 = DIM_C * DIM_C / 2;
    const int GEMM_SMEM = 2 * GSTAGE_WORDS * 4;   // 80 KB
    cudaFuncSetAttribute(gemm_mma_kernel,
                         cudaFuncAttributeMaxDynamicSharedMemorySize, GEMM_SMEM);

    dim3 wgrid(8, 8, 4);
    wsplit4_kernel<<<wgrid, 256>>>(Wq, Wk, Wv, Wo, (uint32_t*)wth, (uint32_t*)wtl);

    const int n4 = BATCH * SEQ_N * DIM_C / 4;
    dim3 sgrid(n4 / 256, 2);
    split2_kernel<<<sgrid, 256>>>((const float4*)x, (const float4*)context,
                                  (uint2*)xh, (uint2*)xl, (uint2*)chh, (uint2*)cl, n4);

    detect_mask_kernel<<<1, 256>>>((const uint32_t*)mask);

    dim3 ggrid(DIM_C / 128, (BATCH * SEQ_N) / 128);   // (4, 64)
    gemm_mma_kernel<<<ggrid, 256, GEMM_SMEM>>>(
        (const uint32_t*)xh, (const uint32_t*)xl,
        (const uint32_t*)wth + 0 * WSZ2, (const uint32_t*)wtl + 0 * WSZ2, bq, qp);

    pack_mask_kernel<<<BATCH * SEQ_N, 128>>>(mask, mb);

    gemm_mma_kernel<<<ggrid, 256, GEMM_SMEM>>>(
        (const uint32_t*)chh, (const uint32_t*)cl,
        (const uint32_t*)wth + 1 * WSZ2, (const uint32_t*)wtl + 1 * WSZ2, bk, kp);
    gemm_mma_kernel<<<ggrid, 256, GEMM_SMEM>>>(
        (const uint32_t*)chh, (const uint32_t*)cl,
        (const uint32_t*)wth + 2 * WSZ2, (const uint32_t*)wtl + 2 * WSZ2, bv, vp);

    const int rope_total = BATCH * SEQ_N * HEADS * 32;
    const float qscale = 0.125f * 1.4426950408889634f;
    rope2d_h_kernel<<<(rope_total + 255) / 256, 256>>>(qp, qh, pos_x, qscale, rope_total);
    rope2d_h_kernel<<<(rope_total + 255) / 256, 256>>>(kp, kh, pos_ctx, 1.0f, rope_total);

    dim3 vgrid(SEQ_M / 64, HEADS, BATCH);
    vtrans_kernel<<<vgrid, 256>>>(vp, vt);

    dim3 agrid(SEQ_N / 128, HEADS, BATCH);
    attn_mma_kernel<<<agrid, 256>>>((const uint32_t*)qh, (const uint32_t*)kh,
                                    vt, mb, (uint32_t*)xh, (uint32_t*)xl);

    gemm_mma_kernel<<<ggrid, 256, GEMM_SMEM>>>(
        (const uint32_t*)xh, (const uint32_t*)xl,
        (const uint32_t*)wth + 3 * WSZ2, (const uint32_t*)wtl + 3 * WSZ2, bo, out);
}